// round 13
// baseline (speedup 1.0000x reference)
#include <cuda_runtime.h>
#include <cuda_fp16.h>
#include <cuda_bf16.h>
#include <cstdint>

#define ROWS_ 8192
#define LSTM_PARTS 8

// weight-split buffer offsets (elements)
#define OFF_PEW1 0
#define OFF_PEW2 2048
#define OFF_WQKV 18432
#define OFF_WO   608256
#define OFF_FFW1 804864
#define OFF_FFW2 1198080
#define OFF_WIH  1591296
#define OFF_PTRW 1853440
#define W_TOTAL  1918976

// ---------------- device scratch ----------------
__device__ float g_x    [ROWS_*256];
__device__ float g_qkv  [ROWS_*768];
__device__ float g_tmp  [ROWS_*256];
__device__ float g_bb   [32*64];
__device__ float g_eproj[ROWS_*256];
__device__ float g_gin  [ROWS_*1024];
__device__ float g_hp   [ROWS_*256];
__device__ float g_hbuf [2*32*256];
__device__ int   g_cnt  [32*256];
// fp16 split pairs
__device__ __half g_whi[W_TOTAL], g_wlo[W_TOTAL];
__device__ __half g_phi[ROWS_*16],  g_plo[ROWS_*16];
__device__ __half g_xhi[ROWS_*256], g_xlo[ROWS_*256];
__device__ __half g_athi[ROWS_*256], g_atlo[ROWS_*256];
__device__ __half g_ffhi[ROWS_*512], g_fflo[ROWS_*512];
__device__ __half g_xihi[ROWS_*256], g_xilo[ROWS_*256];
__device__ __half g_hahi[ROWS_*256], g_halo[ROWS_*256];

__device__ __forceinline__ float sigf(float x) {
    return __fdividef(1.f, 1.f + __expf(-x));
}
__device__ __forceinline__ float tanh_acc(float x) {
    float xx = fminf(fmaxf(x, -15.f), 15.f);
    float e  = __expf(2.f * xx);
    return __fdividef(e - 1.f, e + 1.f);
}
__device__ __forceinline__ float tanh_approx(float x) {
    float y;
    asm("tanh.approx.f32 %0, %1;" : "=f"(y) : "f"(x));
    return y;
}
__device__ __forceinline__ void split2h(float x, __half& hi, __half& lo) {
    hi = __float2half_rn(x);
    lo = __float2half_rn(x - __half2float(hi));
}
__device__ __forceinline__ __half2 sp_hi2(float a, float b) {
    return __halves2half2(__float2half_rn(a), __float2half_rn(b));
}
__device__ __forceinline__ __half2 sp_lo2(float a, float b) {
    __half ha = __float2half_rn(a), hb = __float2half_rn(b);
    return __halves2half2(__float2half_rn(a - __half2float(ha)),
                          __float2half_rn(b - __half2float(hb)));
}
__device__ __forceinline__ void cpa16(__half* dst, const __half* src) {
    uint32_t d = (uint32_t)__cvta_generic_to_shared(dst);
    asm volatile("cp.async.cg.shared.global [%0], [%1], 16;" :: "r"(d), "l"(src));
}

// ---------------- fused splitter: 9 segments in one launch ----------------
struct SplitSegs {
    const float* src[9];
    __half* hi[9];
    __half* lo[9];
    int off[10];
};
__global__ void split_all_kernel(SplitSegs s)
{
    int i = blockIdx.x * 256 + threadIdx.x;
    if (i >= s.off[9]) return;
#pragma unroll
    for (int k = 0; k < 9; k++) {
        if (i < s.off[k+1]) {
            int j = i - s.off[k];
            float v = s.src[k][j];
            __half h, l; split2h(v, h, l);
            s.hi[k][j] = h; s.lo[k][j] = l;
            return;
        }
    }
}

// ---------------- fp16 3-term split GEMM: 64x128 tiles, 2-stage cp.async ---
__device__ __forceinline__ void mma_f16(float* c, const uint32_t* a,
                                        uint32_t b0, uint32_t b1) {
    asm volatile(
        "mma.sync.aligned.m16n8k16.row.col.f32.f16.f16.f32 "
        "{%0,%1,%2,%3}, {%4,%5,%6,%7}, {%8,%9}, {%0,%1,%2,%3};\n"
        : "+f"(c[0]), "+f"(c[1]), "+f"(c[2]), "+f"(c[3])
        : "r"(a[0]), "r"(a[1]), "r"(a[2]), "r"(a[3]), "r"(b0), "r"(b1));
}

#define STR_ 40             // 80B row stride: word-bank 20g mod 32 all-distinct
#define STAGE_H (384*STR_)  // (64+64+128+128) rows

template<int ACT, int SPLIT_OUT, int CHUNK>
__global__ __launch_bounds__(256, 2) void tgemm(
    const __half* __restrict__ Ah, const __half* __restrict__ Al,
    const __half* __restrict__ Wh, const __half* __restrict__ Wl,
    const float* __restrict__ bias, const float* __restrict__ bias2,
    float* __restrict__ C, __half* __restrict__ Ch, __half* __restrict__ Cl,
    int M, int N, int K)
{
    extern __shared__ __half smh[];
    int tid = threadIdx.x;
    int m0 = blockIdx.y * 64, n0 = blockIdx.x * 128;
    int warp = tid >> 5, lane = tid & 31;
    int g = lane >> 2, tg = lane & 3;
    int moff = (warp >> 2) * 32, noff = (warp & 3) * 32;

    constexpr int F8 = CHUNK / 8;       // 16B units per ROW per matrix (full chunk)

    float c_[2][4][4];
#pragma unroll
    for (int i = 0; i < 2; i++)
#pragma unroll
        for (int j = 0; j < 4; j++)
#pragma unroll
            for (int r = 0; r < 4; r++) c_[i][j][r] = 0.f;

    int nch = K / CHUNK;

    // cooperative loader for one chunk into stage st
    auto load_chunk = [&](int st, int kt) {
        __half* S = smh + st * STAGE_H;
        for (int u = tid; u < 384 * F8; u += 256) {
            const __half* src;
            __half* dst;
            if (u < 128 * F8) {                       // A hi/lo (64 rows each)
                int m2 = u >= 64 * F8;
                int v = u - m2 * 64 * F8;
                int row = v / F8, fi = v % F8;
                src = (m2 ? Al : Ah) + (size_t)(m0 + row) * K + kt + fi * 8;
                dst = S + m2 * 64 * STR_ + row * STR_ + fi * 8;
            } else {                                  // B hi/lo (128 rows each)
                int w = u - 128 * F8;
                int m2 = w >= 128 * F8;
                int v = w - m2 * 128 * F8;
                int row = v / F8, fi = v % F8;
                src = (m2 ? Wl : Wh) + (size_t)(n0 + row) * K + kt + fi * 8;
                dst = S + (128 + m2 * 128) * STR_ + row * STR_ + fi * 8;
            }
            cpa16(dst, src);
        }
        asm volatile("cp.async.commit_group;" ::: "memory");
    };

    load_chunk(0, 0);

    for (int ch = 0; ch < nch; ch++) {
        if (ch + 1 < nch) {
            load_chunk((ch + 1) & 1, (ch + 1) * CHUNK);
            asm volatile("cp.async.wait_group 1;" ::: "memory");
        } else {
            asm volatile("cp.async.wait_group 0;" ::: "memory");
        }
        __syncthreads();

        __half* S = smh + (ch & 1) * STAGE_H;
        __half* SA_h = S;
        __half* SA_l = S + 64 * STR_;
        __half* SB_h = S + 128 * STR_;
        __half* SB_l = S + 256 * STR_;
#pragma unroll
        for (int ks = 0; ks < CHUNK / 16; ks++) {
            int kb = ks * 16 + 2 * tg;
            uint32_t ah[2][4], al[2][4];
#pragma unroll
            for (int mi = 0; mi < 2; mi++) {
                int r = (moff + mi * 16 + g) * STR_;
                ah[mi][0] = *(const uint32_t*)(SA_h + r + kb);
                ah[mi][1] = *(const uint32_t*)(SA_h + r + 8 * STR_ + kb);
                ah[mi][2] = *(const uint32_t*)(SA_h + r + kb + 8);
                ah[mi][3] = *(const uint32_t*)(SA_h + r + 8 * STR_ + kb + 8);
                al[mi][0] = *(const uint32_t*)(SA_l + r + kb);
                al[mi][1] = *(const uint32_t*)(SA_l + r + 8 * STR_ + kb);
                al[mi][2] = *(const uint32_t*)(SA_l + r + kb + 8);
                al[mi][3] = *(const uint32_t*)(SA_l + r + 8 * STR_ + kb + 8);
            }
#pragma unroll
            for (int ni = 0; ni < 4; ni++) {
                int n = (noff + ni * 8 + g) * STR_;
                uint32_t bh0 = *(const uint32_t*)(SB_h + n + kb);
                uint32_t bh1 = *(const uint32_t*)(SB_h + n + kb + 8);
                uint32_t bl0 = *(const uint32_t*)(SB_l + n + kb);
                uint32_t bl1 = *(const uint32_t*)(SB_l + n + kb + 8);
#pragma unroll
                for (int mi = 0; mi < 2; mi++) {
                    mma_f16(c_[mi][ni], ah[mi], bh0, bh1);
                    mma_f16(c_[mi][ni], ah[mi], bl0, bl1);
                    mma_f16(c_[mi][ni], al[mi], bh0, bh1);
                }
            }
        }
        __syncthreads();
    }

    // epilogue
#pragma unroll
    for (int ni = 0; ni < 4; ni++) {
        int cc = n0 + noff + ni * 8 + 2 * tg;
        float bx = bias[cc], by = bias[cc + 1];
        if (bias2) { bx += bias2[cc]; by += bias2[cc + 1]; }
#pragma unroll
        for (int mi = 0; mi < 2; mi++) {
            size_t r0 = (size_t)(m0 + moff + mi * 16 + g);
            size_t r1 = r0 + 8;
            float v0 = c_[mi][ni][0] + bx, v1 = c_[mi][ni][1] + by;
            float v2 = c_[mi][ni][2] + bx, v3 = c_[mi][ni][3] + by;
            if (ACT) {
                v0 = fmaxf(v0, 0.f); v1 = fmaxf(v1, 0.f);
                v2 = fmaxf(v2, 0.f); v3 = fmaxf(v3, 0.f);
            }
            if (SPLIT_OUT) {
                *(__half2*)(Ch + r0*N + cc) = sp_hi2(v0, v1);
                *(__half2*)(Cl + r0*N + cc) = sp_lo2(v0, v1);
                *(__half2*)(Ch + r1*N + cc) = sp_hi2(v2, v3);
                *(__half2*)(Cl + r1*N + cc) = sp_lo2(v2, v3);
            } else {
                *(float2*)(C + r0*N + cc) = make_float2(v0, v1);
                *(float2*)(C + r1*N + cc) = make_float2(v2, v3);
            }
        }
    }
}

// ---------------- bin encoder ----------------
__global__ void bin_enc_kernel(const float* __restrict__ bin,
                               const float* __restrict__ W1, const float* __restrict__ b1,
                               const float* __restrict__ W2, const float* __restrict__ b2,
                               float* __restrict__ bb)
{
    __shared__ float h1s[64];
    int b = blockIdx.x, j = threadIdx.x;
    float x0 = bin[b*2], x1 = bin[b*2+1];
    float h = fmaxf(fmaf(x0, W1[j*2], fmaf(x1, W1[j*2+1], b1[j])), 0.f);
    h1s[j] = h;
    __syncthreads();
    float acc = b2[j];
#pragma unroll 8
    for (int k = 0; k < 64; k++) acc = fmaf(h1s[k], W2[j*64 + k], acc);
    bb[b*64 + j] = acc;
}

// ---------------- concat ----------------
__global__ void concat_kernel(const float* __restrict__ p, const float* __restrict__ bb,
                              const float* __restrict__ pos, float* __restrict__ x,
                              __half* __restrict__ xhi, __half* __restrict__ xlo)
{
    int idx = blockIdx.x * 128 + threadIdx.x;
    int r = idx >> 6, c4 = idx & 63;
    int b = r >> 8, s = r & 255;
    float4 v;
    if (c4 < 32)      v = ((const float4*)(p   + (size_t)r*128))[c4];
    else if (c4 < 48) v = ((const float4*)(bb  + (size_t)b*64))[c4-32];
    else              v = ((const float4*)(pos + (size_t)s*64))[c4-48];
    ((float4*)(x + (size_t)r*256))[c4] = v;
    __half2* ph = (__half2*)(xhi + (size_t)r*256);
    __half2* pl = (__half2*)(xlo + (size_t)r*256);
    ph[c4*2]   = sp_hi2(v.x, v.y); pl[c4*2]   = sp_lo2(v.x, v.y);
    ph[c4*2+1] = sp_hi2(v.z, v.w); pl[c4*2+1] = sp_lo2(v.z, v.w);
}

// ---------------- attention: 256 threads, one row/thread ----------------
__global__ __launch_bounds__(256, 2) void attn_kernel(const float* __restrict__ qkv,
                                                      __half* __restrict__ ohi,
                                                      __half* __restrict__ olo)
{
    extern __shared__ float sm[];
    float* Ks = sm;
    float* Vs = sm + 256*32;
    int b = blockIdx.x >> 3, h = blockIdx.x & 7;
    int tid = threadIdx.x;
    const float scale = 0.17677669529663687f;

    {
        const float4* ksrc = (const float4*)(qkv + (size_t)(b*256 + tid)*768 + 256 + h*32);
        const float4* vsrc = (const float4*)(qkv + (size_t)(b*256 + tid)*768 + 512 + h*32);
        float4* kd = (float4*)(Ks + tid*32);
        float4* vd = (float4*)(Vs + tid*32);
#pragma unroll
        for (int i = 0; i < 8; i++) { kd[i] = ksrc[i]; vd[i] = vsrc[i]; }
    }
    float q[32], acc[32];
    {
        const float4* qf = (const float4*)(qkv + (size_t)(b*256 + tid)*768 + h*32);
#pragma unroll
        for (int i = 0; i < 8; i++) {
            float4 t = qf[i];
            q[i*4+0]=t.x; q[i*4+1]=t.y; q[i*4+2]=t.z; q[i*4+3]=t.w;
        }
    }
#pragma unroll
    for (int i = 0; i < 32; i++) acc[i] = 0.f;
    __syncthreads();

    float lsum = 0.f;
    for (int k = 0; k < 256; k++) {
        const float4* kr = (const float4*)(Ks + k*32);
        float s0 = 0.f, s1 = 0.f, s2 = 0.f, s3 = 0.f;
#pragma unroll
        for (int i4 = 0; i4 < 8; i4 += 4) {
            float4 k0 = kr[i4], k1 = kr[i4+1], k2 = kr[i4+2], k3 = kr[i4+3];
            s0 = fmaf(q[i4*4+0],  k0.x, s0); s0 = fmaf(q[i4*4+1],  k0.y, s0);
            s0 = fmaf(q[i4*4+2],  k0.z, s0); s0 = fmaf(q[i4*4+3],  k0.w, s0);
            s1 = fmaf(q[i4*4+4],  k1.x, s1); s1 = fmaf(q[i4*4+5],  k1.y, s1);
            s1 = fmaf(q[i4*4+6],  k1.z, s1); s1 = fmaf(q[i4*4+7],  k1.w, s1);
            s2 = fmaf(q[i4*4+8],  k2.x, s2); s2 = fmaf(q[i4*4+9],  k2.y, s2);
            s2 = fmaf(q[i4*4+10], k2.z, s2); s2 = fmaf(q[i4*4+11], k2.w, s2);
            s3 = fmaf(q[i4*4+12], k3.x, s3); s3 = fmaf(q[i4*4+13], k3.y, s3);
            s3 = fmaf(q[i4*4+14], k3.z, s3); s3 = fmaf(q[i4*4+15], k3.w, s3);
        }
        float p = __expf(((s0 + s1) + (s2 + s3)) * scale);
        lsum += p;
        const float4* vr = (const float4*)(Vs + k*32);
#pragma unroll
        for (int i4 = 0; i4 < 8; i4++) {
            float4 vv = vr[i4];
            acc[i4*4+0] = fmaf(p, vv.x, acc[i4*4+0]);
            acc[i4*4+1] = fmaf(p, vv.y, acc[i4*4+1]);
            acc[i4*4+2] = fmaf(p, vv.z, acc[i4*4+2]);
            acc[i4*4+3] = fmaf(p, vv.w, acc[i4*4+3]);
        }
    }
    float inv = __fdividef(1.f, lsum);
    __half2* oh = (__half2*)(ohi + (size_t)(b*256 + tid)*256 + h*32);
    __half2* ol = (__half2*)(olo + (size_t)(b*256 + tid)*256 + h*32);
#pragma unroll
    for (int i4 = 0; i4 < 8; i4++) {
        float rx = acc[i4*4+0]*inv, ry = acc[i4*4+1]*inv;
        float rz = acc[i4*4+2]*inv, rw = acc[i4*4+3]*inv;
        oh[i4*2]   = sp_hi2(rx, ry); ol[i4*2]   = sp_lo2(rx, ry);
        oh[i4*2+1] = sp_hi2(rz, rw); ol[i4*2+1] = sp_lo2(rz, rw);
    }
}

// ---------------- residual + LayerNorm ----------------
__global__ void add_ln_kernel(const float* __restrict__ x, const float* __restrict__ y,
                              const float* __restrict__ g, const float* __restrict__ be,
                              float* __restrict__ out,
                              __half* __restrict__ ohi, __half* __restrict__ olo)
{
    int warp = threadIdx.x >> 5, lane = threadIdx.x & 31;
    size_t row = (size_t)blockIdx.x * 8 + warp;
    const float4* xr = (const float4*)(x + row*256);
    const float4* yr = (const float4*)(y + row*256);
    float4 a0 = xr[lane*2], a1 = xr[lane*2+1];
    float4 c0 = yr[lane*2], c1 = yr[lane*2+1];
    float v[8];
    v[0]=a0.x+c0.x; v[1]=a0.y+c0.y; v[2]=a0.z+c0.z; v[3]=a0.w+c0.w;
    v[4]=a1.x+c1.x; v[5]=a1.y+c1.y; v[6]=a1.z+c1.z; v[7]=a1.w+c1.w;
    float s = 0.f, s2 = 0.f;
#pragma unroll
    for (int i = 0; i < 8; i++) { s += v[i]; s2 = fmaf(v[i], v[i], s2); }
#pragma unroll
    for (int o = 16; o > 0; o >>= 1) {
        s  += __shfl_xor_sync(0xffffffffu, s,  o);
        s2 += __shfl_xor_sync(0xffffffffu, s2, o);
    }
    float mean = s * (1.f/256.f);
    float var  = s2 * (1.f/256.f) - mean*mean;
    float rstd = rsqrtf(var + 1e-5f);
    const float4* gf = (const float4*)(g + lane*8);
    const float4* bf = (const float4*)(be + lane*8);
    float4 g0 = gf[0], g1 = gf[1], b0 = bf[0], b1 = bf[1];
    float r[8];
    r[0] = (v[0]-mean)*rstd*g0.x + b0.x; r[1] = (v[1]-mean)*rstd*g0.y + b0.y;
    r[2] = (v[2]-mean)*rstd*g0.z + b0.z; r[3] = (v[3]-mean)*rstd*g0.w + b0.w;
    r[4] = (v[4]-mean)*rstd*g1.x + b1.x; r[5] = (v[5]-mean)*rstd*g1.y + b1.y;
    r[6] = (v[6]-mean)*rstd*g1.z + b1.z; r[7] = (v[7]-mean)*rstd*g1.w + b1.w;
    ((float4*)(out + row*256))[lane*2]   = make_float4(r[0], r[1], r[2], r[3]);
    ((float4*)(out + row*256))[lane*2+1] = make_float4(r[4], r[5], r[6], r[7]);
    __half2* ph = (__half2*)(ohi + row*256);
    __half2* pl = (__half2*)(olo + row*256);
#pragma unroll
    for (int i = 0; i < 4; i++) {
        ph[lane*4 + i] = sp_hi2(r[i*2], r[i*2+1]);
        pl[lane*4 + i] = sp_lo2(r[i*2], r[i*2+1]);
    }
}

// ---------------- gather ----------------
__global__ void gather_kernel(const float* __restrict__ enc, const int* __restrict__ target,
                              __half* __restrict__ xhi, __half* __restrict__ xlo)
{
    int idx = blockIdx.x * 256 + threadIdx.x;
    int r = idx >> 6, c4 = idx & 63;
    int t = r >> 5, b = r & 31;
    float4 val = make_float4(0.f, 0.f, 0.f, 0.f);
    if (t > 0) {
        int tgt = target[b*256 + t - 1];
        val = ((const float4*)(enc + (size_t)(b*256 + tgt)*256))[c4];
    }
    __half2* ph = (__half2*)(xhi + (size_t)r*256);
    __half2* pl = (__half2*)(xlo + (size_t)r*256);
    ph[c4*2]   = sp_hi2(val.x, val.y); pl[c4*2]   = sp_lo2(val.x, val.y);
    ph[c4*2+1] = sp_hi2(val.z, val.w); pl[c4*2+1] = sp_lo2(val.z, val.w);
}

// ---------------- lstm init ----------------
__global__ void lstm_init_kernel(int* __restrict__ cnt)
{
    int idx = blockIdx.x * 256 + threadIdx.x;
    if (idx < 32*256) cnt[idx] = 0;
}

// ---------------- LSTM: 256 CTAs, Whh in registers ----------------
__global__ __launch_bounds__(256, 1) void lstm_kernel(
    const float* __restrict__ gin,
    const float* __restrict__ Whh,
    __half* __restrict__ hallhi, __half* __restrict__ halllo,
    float* __restrict__ hbuf,
    int* __restrict__ cnt)
{
    __shared__ float h_s[256];
    __shared__ float g_s[128];
    int b = blockIdx.x >> 3, part = blockIdx.x & 7;
    int tid = threadIdx.x;
    int p = tid >> 1, half = tid & 1;
    int gate = p >> 5, jj = p & 31;
    int col = gate * 256 + part * 32 + jj;

    float w[128];
    {
        const float4* wsrc = (const float4*)(Whh + (size_t)col * 256 + half * 128);
#pragma unroll
        for (int i = 0; i < 32; i++) {
            float4 v = wsrc[i];
            w[i*4+0]=v.x; w[i*4+1]=v.y; w[i*4+2]=v.z; w[i*4+3]=v.w;
        }
    }
    float c = 0.f;
    if (tid < 256) h_s[tid] = 0.f;
    __syncthreads();

    volatile int* vcnt = cnt + b * 256;
    for (int t = 0; t < 256; t++) {
        if (t > 0) {
            if (tid == 0) { while (vcnt[t-1] < LSTM_PARTS) { } }
            __syncthreads();
            const float4* hsrc = (const float4*)(hbuf + ((size_t)((t & 1) * 32 + b)) * 256);
            if (tid < 64) *(float4*)&h_s[tid*4] = __ldcg(hsrc + tid);
            __syncthreads();
        }
        float a0 = 0.f, a1 = 0.f, a2 = 0.f, a3 = 0.f;
        const float4* h4 = (const float4*)&h_s[half * 128];
#pragma unroll
        for (int k4 = 0; k4 < 32; k4 += 4) {
            float4 h0 = h4[k4], h1 = h4[k4+1], h2 = h4[k4+2], h3 = h4[k4+3];
            a0 = fmaf(w[k4*4+0],  h0.x, a0); a0 = fmaf(w[k4*4+1],  h0.y, a0);
            a0 = fmaf(w[k4*4+2],  h0.z, a0); a0 = fmaf(w[k4*4+3],  h0.w, a0);
            a1 = fmaf(w[k4*4+4],  h1.x, a1); a1 = fmaf(w[k4*4+5],  h1.y, a1);
            a1 = fmaf(w[k4*4+6],  h1.z, a1); a1 = fmaf(w[k4*4+7],  h1.w, a1);
            a2 = fmaf(w[k4*4+8],  h2.x, a2); a2 = fmaf(w[k4*4+9],  h2.y, a2);
            a2 = fmaf(w[k4*4+10], h2.z, a2); a2 = fmaf(w[k4*4+11], h2.w, a2);
            a3 = fmaf(w[k4*4+12], h3.x, a3); a3 = fmaf(w[k4*4+13], h3.y, a3);
            a3 = fmaf(w[k4*4+14], h3.z, a3); a3 = fmaf(w[k4*4+15], h3.w, a3);
        }
        float acc = (a0 + a1) + (a2 + a3);
        acc += __shfl_xor_sync(0xffffffffu, acc, 1);
        if (half == 0) {
            float gv = __ldcg(gin + ((size_t)(t*32 + b))*1024 + col);
            g_s[p] = acc + gv;
        }
        __syncthreads();
        if (tid < 32) {
            float gi = g_s[tid], gf = g_s[32+tid], gg = g_s[64+tid], go = g_s[96+tid];
            c = sigf(gf) * c + sigf(gi) * tanh_acc(gg);
            float h = sigf(go) * tanh_acc(c);
            int colh = part*32 + tid;
            hbuf[((size_t)(((t+1) & 1) * 32 + b))*256 + colh] = h;
            __half hh, hl; split2h(h, hh, hl);
            size_t oidx = ((size_t)(t*32 + b))*256 + colh;
            hallhi[oidx] = hh;
            halllo[oidx] = hl;
        }
        __threadfence();
        __syncthreads();
        if (tid == 0) atomicAdd(cnt + b*256 + t, 1);
    }
}

// ---------------- logits: transposed smem, conflict-free reads -------------
#define LP 34
__global__ __launch_bounds__(256, 3) void logits_kernel(
    const float* __restrict__ hp, const float* __restrict__ ep,
    const float* __restrict__ v, float* __restrict__ out)
{
    extern __shared__ float sm[];
    float* hpsT = sm;                 // [256 j][LP] col r = t-row
    float* epsT = sm + 256*LP;        // [256 j][LP] col r = i-row
    float* vs   = sm + 2*256*LP;
    int b = blockIdx.z, tt = blockIdx.y*32, it = blockIdx.x*32;
    int tid = threadIdx.x;
    for (int idx = tid; idx < 32*64; idx += 256) {
        int r = idx >> 6, c4 = idx & 63;
        float4 hv = ((const float4*)(hp + ((size_t)(tt+r)*32 + b)*256))[c4];
        float4 ev = ((const float4*)(ep + ((size_t)b*256 + it + r)*256))[c4];
        int c = c4 * 4;
        hpsT[(c+0)*LP + r] = hv.x; hpsT[(c+1)*LP + r] = hv.y;
        hpsT[(c+2)*LP + r] = hv.z; hpsT[(c+3)*LP + r] = hv.w;
        epsT[(c+0)*LP + r] = ev.x; epsT[(c+1)*LP + r] = ev.y;
        epsT[(c+2)*LP + r] = ev.z; epsT[(c+3)*LP + r] = ev.w;
    }
    if (tid < 64) *(float4*)&vs[tid*4] = ((const float4*)v)[tid];
    __syncthreads();
    int ti = (tid >> 4) * 2, ii = (tid & 15) * 2;
    float s00=0.f, s01=0.f, s10=0.f, s11=0.f;
    for (int j = 0; j < 256; j++) {
        float2 hh = *(const float2*)&hpsT[j*LP + ti];
        float2 ee = *(const float2*)&epsT[j*LP + ii];
        float vj = vs[j];
        s00 = fmaf(vj, tanh_approx(hh.x + ee.x), s00);
        s01 = fmaf(vj, tanh_approx(hh.x + ee.y), s01);
        s10 = fmaf(vj, tanh_approx(hh.y + ee.x), s10);
        s11 = fmaf(vj, tanh_approx(hh.y + ee.y), s11);
    }
    size_t base = ((size_t)b*256 + tt + ti)*256 + it + ii;
    out[base]       = s00; out[base+1]   = s01;
    out[base+256]   = s10; out[base+257] = s11;
}

// ---------------- host ----------------
#define TG_SMEM (2*STAGE_H*2)          // 2 stages x 15360 halves x 2B = 61440
#define LG_SMEM ((2*256*LP + 256)*4)   // 70656

extern "C" void kernel_launch(void* const* d_in, const int* in_sizes, int n_in,
                              void* d_out, int out_size)
{
    const float* parts    = (const float*)d_in[0];
    const float* bin_info = (const float*)d_in[1];
    const int*   target   = (const int*)  d_in[2];
    const float* pe_W1 = (const float*)d_in[3];
    const float* pe_b1 = (const float*)d_in[4];
    const float* pe_W2 = (const float*)d_in[5];
    const float* pe_b2 = (const float*)d_in[6];
    const float* be_W1 = (const float*)d_in[7];
    const float* be_b1 = (const float*)d_in[8];
    const float* be_W2 = (const float*)d_in[9];
    const float* be_b2 = (const float*)d_in[10];
    const float* pos_emb = (const float*)d_in[11];
    const float* tr_Wqkv = (const float*)d_in[12];
    const float* tr_bqkv = (const float*)d_in[13];
    const float* tr_Wo   = (const float*)d_in[14];
    const float* tr_bo   = (const float*)d_in[15];
    const float* tr_ln1_g = (const float*)d_in[16];
    const float* tr_ln1_b = (const float*)d_in[17];
    const float* tr_ff_W1 = (const float*)d_in[18];
    const float* tr_ff_b1 = (const float*)d_in[19];
    const float* tr_ff_W2 = (const float*)d_in[20];
    const float* tr_ff_b2 = (const float*)d_in[21];
    const float* tr_ln2_g = (const float*)d_in[22];
    const float* tr_ln2_b = (const float*)d_in[23];
    const float* lstm_Wih = (const float*)d_in[24];
    const float* lstm_Whh = (const float*)d_in[25];
    const float* lstm_bih = (const float*)d_in[26];
    const float* lstm_bhh = (const float*)d_in[27];
    const float* ptr_W = (const float*)d_in[28];
    const float* ptr_b = (const float*)d_in[29];
    const float* ptr_v = (const float*)d_in[30];
    float* out = (float*)d_out;

    float *x_, *qkv_, *tmp_, *bb_, *ep_, *gin_, *hp_, *hbuf_;
    __half *whi_, *wlo_, *phi_, *plo_, *xhi_, *xlo_, *athi_, *atlo_;
    __half *ffhi_, *fflo_, *xihi_, *xilo_, *hahi_, *halo_;
    int* cnt_;
    cudaGetSymbolAddress((void**)&x_,    g_x);
    cudaGetSymbolAddress((void**)&qkv_,  g_qkv);
    cudaGetSymbolAddress((void**)&tmp_,  g_tmp);
    cudaGetSymbolAddress((void**)&bb_,   g_bb);
    cudaGetSymbolAddress((void**)&ep_,   g_eproj);
    cudaGetSymbolAddress((void**)&gin_,  g_gin);
    cudaGetSymbolAddress((void**)&hp_,   g_hp);
    cudaGetSymbolAddress((void**)&hbuf_, g_hbuf);
    cudaGetSymbolAddress((void**)&cnt_,  g_cnt);
    cudaGetSymbolAddress((void**)&whi_,  g_whi);
    cudaGetSymbolAddress((void**)&wlo_,  g_wlo);
    cudaGetSymbolAddress((void**)&phi_,  g_phi);
    cudaGetSymbolAddress((void**)&plo_,  g_plo);
    cudaGetSymbolAddress((void**)&xhi_,  g_xhi);
    cudaGetSymbolAddress((void**)&xlo_,  g_xlo);
    cudaGetSymbolAddress((void**)&athi_, g_athi);
    cudaGetSymbolAddress((void**)&atlo_, g_atlo);
    cudaGetSymbolAddress((void**)&ffhi_, g_ffhi);
    cudaGetSymbolAddress((void**)&fflo_, g_fflo);
    cudaGetSymbolAddress((void**)&xihi_, g_xihi);
    cudaGetSymbolAddress((void**)&xilo_, g_xilo);
    cudaGetSymbolAddress((void**)&hahi_, g_hahi);
    cudaGetSymbolAddress((void**)&halo_, g_halo);

    cudaFuncSetAttribute(attn_kernel,   cudaFuncAttributeMaxDynamicSharedMemorySize, 65536);
    cudaFuncSetAttribute(logits_kernel, cudaFuncAttributeMaxDynamicSharedMemorySize, LG_SMEM);
    cudaFuncSetAttribute(tgemm<1,1,16>, cudaFuncAttributeMaxDynamicSharedMemorySize, TG_SMEM);
    cudaFuncSetAttribute(tgemm<0,0,32>, cudaFuncAttributeMaxDynamicSharedMemorySize, TG_SMEM);
    cudaFuncSetAttribute(tgemm<1,1,32>, cudaFuncAttributeMaxDynamicSharedMemorySize, TG_SMEM);

    // fused weight + input splits (9 segments, one launch)
    SplitSegs ss;
    ss.src[0]=pe_W1;    ss.hi[0]=whi_+OFF_PEW1; ss.lo[0]=wlo_+OFF_PEW1;
    ss.src[1]=pe_W2;    ss.hi[1]=whi_+OFF_PEW2; ss.lo[1]=wlo_+OFF_PEW2;
    ss.src[2]=tr_Wqkv;  ss.hi[2]=whi_+OFF_WQKV; ss.lo[2]=wlo_+OFF_WQKV;
    ss.src[3]=tr_Wo;    ss.hi[3]=whi_+OFF_WO;   ss.lo[3]=wlo_+OFF_WO;
    ss.src[4]=tr_ff_W1; ss.hi[4]=whi_+OFF_FFW1; ss.lo[4]=wlo_+OFF_FFW1;
    ss.src[5]=tr_ff_W2; ss.hi[5]=whi_+OFF_FFW2; ss.lo[5]=wlo_+OFF_FFW2;
    ss.src[6]=lstm_Wih; ss.hi[6]=whi_+OFF_WIH;  ss.lo[6]=wlo_+OFF_WIH;
    ss.src[7]=ptr_W;    ss.hi[7]=whi_+OFF_PTRW; ss.lo[7]=wlo_+OFF_PTRW;
    ss.src[8]=parts;    ss.hi[8]=phi_;          ss.lo[8]=plo_;
    ss.off[0]=0;        ss.off[1]=2048;    ss.off[2]=18432;   ss.off[3]=608256;
    ss.off[4]=804864;   ss.off[5]=1198080; ss.off[6]=1591296; ss.off[7]=1853440;
    ss.off[8]=1918976;  ss.off[9]=2050048;
    split_all_kernel<<<(2050048 + 255)/256, 256>>>(ss);

    // encoders
    bin_enc_kernel<<<32, 64>>>(bin_info, be_W1, be_b1, be_W2, be_b2, bb_);
    tgemm<1,1,16><<<dim3(1,128), 256, TG_SMEM>>>(phi_, plo_, whi_+OFF_PEW1, wlo_+OFF_PEW1,
                                    pe_b1, nullptr, nullptr, athi_, atlo_, ROWS_, 128, 16);
    tgemm<0,0,32><<<dim3(1,128), 256, TG_SMEM>>>(athi_, atlo_, whi_+OFF_PEW2, wlo_+OFF_PEW2,
                                    pe_b2, nullptr, tmp_, nullptr, nullptr, ROWS_, 128, 128);
    concat_kernel<<<4096, 128>>>(tmp_, bb_, pos_emb, x_, xhi_, xlo_);

    // transformer layers
    for (int l = 0; l < 3; l++) {
        tgemm<0,0,32><<<dim3(6,128), 256, TG_SMEM>>>(xhi_, xlo_,
            whi_+OFF_WQKV + (size_t)l*196608, wlo_+OFF_WQKV + (size_t)l*196608,
            tr_bqkv + l*768, nullptr, qkv_, nullptr, nullptr, ROWS_, 768, 256);
        attn_kernel<<<256, 256, 65536>>>(qkv_, athi_, atlo_);
        tgemm<0,0,32><<<dim3(2,128), 256, TG_SMEM>>>(athi_, atlo_,
            whi_+OFF_WO + (size_t)l*65536, wlo_+OFF_WO + (size_t)l*65536,
            tr_bo + l*256, nullptr, tmp_, nullptr, nullptr, ROWS_, 256, 256);
        add_ln_kernel<<<1024, 256>>>(x_, tmp_, tr_ln1_g + l*256, tr_ln1_b + l*256,
                                     x_, xhi_, xlo_);
        tgemm<1,1,32><<<dim3(4,128), 256, TG_SMEM>>>(xhi_, xlo_,
            whi_+OFF_FFW1 + (size_t)l*131072, wlo_+OFF_FFW1 + (size_t)l*131072,
            tr_ff_b1 + l*512, nullptr, nullptr, ffhi_, fflo_, ROWS_, 512, 256);
        tgemm<0,0,32><<<dim3(2,128), 256, TG_SMEM>>>(ffhi_, fflo_,
            whi_+OFF_FFW2 + (size_t)l*131072, wlo_+OFF_FFW2 + (size_t)l*131072,
            tr_ff_b2 + l*256, nullptr, tmp_, nullptr, nullptr, ROWS_, 256, 512);
        add_ln_kernel<<<1024, 256>>>(x_, tmp_, tr_ln2_g + l*256, tr_ln2_b + l*256,
                                     x_, xhi_, xlo_);
    }

    // pointer decode
    tgemm<0,0,32><<<dim3(2,128), 256, TG_SMEM>>>(xhi_, xlo_, whi_+OFF_PTRW, wlo_+OFF_PTRW,
                                    ptr_b, nullptr, ep_, nullptr, nullptr, ROWS_, 256, 256);
    gather_kernel<<<2048, 256>>>(x_, target, xihi_, xilo_);
    tgemm<0,0,32><<<dim3(8,128), 256, TG_SMEM>>>(xihi_, xilo_, whi_+OFF_WIH, wlo_+OFF_WIH,
                                    lstm_bih, lstm_bhh, gin_, nullptr, nullptr, ROWS_, 1024, 256);
    lstm_init_kernel<<<32, 256>>>(cnt_);
    lstm_kernel<<<256, 256>>>(gin_, lstm_Whh, hahi_, halo_, hbuf_, cnt_);
    tgemm<0,0,32><<<dim3(2,128), 256, TG_SMEM>>>(hahi_, halo_, whi_+OFF_PTRW, wlo_+OFF_PTRW,
                                    ptr_b, nullptr, hp_, nullptr, nullptr, ROWS_, 256, 256);
    logits_kernel<<<dim3(8,8,32), 256, LG_SMEM>>>(hp_, ep_, ptr_v, out);
}

// round 14
// speedup vs baseline: 1.0179x; 1.0179x over previous
#include <cuda_runtime.h>
#include <cuda_fp16.h>
#include <cuda_bf16.h>
#include <cstdint>

#define ROWS_ 8192
#define LSTM_PARTS 8

// weight-split buffer offsets (elements)
#define OFF_PEW1 0
#define OFF_PEW2 2048
#define OFF_WQKV 18432
#define OFF_WO   608256
#define OFF_FFW1 804864
#define OFF_FFW2 1198080
#define OFF_WIH  1591296
#define OFF_PTRW 1853440
#define W_TOTAL  1918976

// ---------------- device scratch ----------------
__device__ float g_x    [ROWS_*256];
__device__ float g_qkv  [ROWS_*768];
__device__ float g_tmp  [ROWS_*256];
__device__ float g_bb   [32*64];
__device__ float g_eproj[ROWS_*256];
__device__ float g_gin  [ROWS_*1024];
__device__ float g_hp   [ROWS_*256];
__device__ float g_hbuf [2*32*256];
__device__ int   g_cnt  [32*256];
// fp16 split pairs
__device__ __half g_whi[W_TOTAL], g_wlo[W_TOTAL];
__device__ __half g_phi[ROWS_*16],  g_plo[ROWS_*16];
__device__ __half g_xhi[ROWS_*256], g_xlo[ROWS_*256];
__device__ __half g_athi[ROWS_*256], g_atlo[ROWS_*256];
__device__ __half g_ffhi[ROWS_*512], g_fflo[ROWS_*512];
__device__ __half g_xihi[ROWS_*256], g_xilo[ROWS_*256];
__device__ __half g_hahi[ROWS_*256], g_halo[ROWS_*256];

__device__ __forceinline__ float sigf(float x) {
    return __fdividef(1.f, 1.f + __expf(-x));
}
__device__ __forceinline__ float tanh_acc(float x) {
    float xx = fminf(fmaxf(x, -15.f), 15.f);
    float e  = __expf(2.f * xx);
    return __fdividef(e - 1.f, e + 1.f);
}
__device__ __forceinline__ float tanh_approx(float x) {
    float y;
    asm("tanh.approx.f32 %0, %1;" : "=f"(y) : "f"(x));
    return y;
}
__device__ __forceinline__ void split2h(float x, __half& hi, __half& lo) {
    hi = __float2half_rn(x);
    lo = __float2half_rn(x - __half2float(hi));
}
__device__ __forceinline__ __half2 sp_hi2(float a, float b) {
    return __halves2half2(__float2half_rn(a), __float2half_rn(b));
}
__device__ __forceinline__ __half2 sp_lo2(float a, float b) {
    __half ha = __float2half_rn(a), hb = __float2half_rn(b);
    return __halves2half2(__float2half_rn(a - __half2float(ha)),
                          __float2half_rn(b - __half2float(hb)));
}
__device__ __forceinline__ void cpa16(__half* dst, const __half* src) {
    uint32_t d = (uint32_t)__cvta_generic_to_shared(dst);
    asm volatile("cp.async.cg.shared.global [%0], [%1], 16;" :: "r"(d), "l"(src));
}

// ---------------- fused splitter: 9 segments in one launch ----------------
struct SplitSegs {
    const float* src[9];
    __half* hi[9];
    __half* lo[9];
    int off[10];
};
__global__ void split_all_kernel(SplitSegs s)
{
    int i = blockIdx.x * 256 + threadIdx.x;
    if (i >= s.off[9]) return;
#pragma unroll
    for (int k = 0; k < 9; k++) {
        if (i < s.off[k+1]) {
            int j = i - s.off[k];
            float v = s.src[k][j];
            __half h, l; split2h(v, h, l);
            s.hi[k][j] = h; s.lo[k][j] = l;
            return;
        }
    }
}

// ---------------- fp16 3-term split GEMM, 128x128 tiles, 2-stage cp.async --
__device__ __forceinline__ void mma_f16(float* c, const uint32_t* a,
                                        uint32_t b0, uint32_t b1) {
    asm volatile(
        "mma.sync.aligned.m16n8k16.row.col.f32.f16.f16.f32 "
        "{%0,%1,%2,%3}, {%4,%5,%6,%7}, {%8,%9}, {%0,%1,%2,%3};\n"
        : "+f"(c[0]), "+f"(c[1]), "+f"(c[2]), "+f"(c[3])
        : "r"(a[0]), "r"(a[1]), "r"(a[2]), "r"(a[3]), "r"(b0), "r"(b1));
}

#define STR_ 40             // 80B row stride: word-bank 20g mod 32 all-distinct
#define STAGE_H (4*128*STR_)

template<int ACT, int SPLIT_OUT, int CHUNK>
__global__ __launch_bounds__(256, 2) void tgemm(
    const __half* __restrict__ Ah, const __half* __restrict__ Al,
    const __half* __restrict__ Wh, const __half* __restrict__ Wl,
    const float* __restrict__ bias, const float* __restrict__ bias2,
    float* __restrict__ C, __half* __restrict__ Ch, __half* __restrict__ Cl,
    int M, int N, int K)
{
    extern __shared__ __half smh[];
    int tid = threadIdx.x;
    int m0 = blockIdx.y * 128, n0 = blockIdx.x * 128;
    int warp = tid >> 5, lane = tid & 31;
    int g = lane >> 2, tg = lane & 3;
    int moff = (warp >> 2) * 64, noff = (warp & 3) * 32;

    constexpr int F4 = CHUNK / 16;      // 16B units per thread per matrix
    int row = tid >> 1;
    int fbase = (tid & 1) * F4;

    const __half* Ahp = Ah + (size_t)(m0 + row) * K;
    const __half* Alp = Al + (size_t)(m0 + row) * K;
    const __half* Whp = Wh + (size_t)(n0 + row) * K;
    const __half* Wlp = Wl + (size_t)(n0 + row) * K;

    float c_[4][4][4];
#pragma unroll
    for (int i = 0; i < 4; i++)
#pragma unroll
        for (int j = 0; j < 4; j++)
#pragma unroll
            for (int r = 0; r < 4; r++) c_[i][j][r] = 0.f;

    int nch = K / CHUNK;

    // preload chunk 0 into stage 0
    {
        __half* S = smh;
#pragma unroll
        for (int j = 0; j < F4; j++) {
            int fi = fbase + j;
            cpa16(S + 0*128*STR_ + row*STR_ + fi*8, Ahp + fi*8);
            cpa16(S + 1*128*STR_ + row*STR_ + fi*8, Alp + fi*8);
            cpa16(S + 2*128*STR_ + row*STR_ + fi*8, Whp + fi*8);
            cpa16(S + 3*128*STR_ + row*STR_ + fi*8, Wlp + fi*8);
        }
        asm volatile("cp.async.commit_group;" ::: "memory");
    }

    for (int ch = 0; ch < nch; ch++) {
        if (ch + 1 < nch) {
            __half* S = smh + ((ch + 1) & 1) * STAGE_H;
            int kt = (ch + 1) * CHUNK;
#pragma unroll
            for (int j = 0; j < F4; j++) {
                int fi = fbase + j;
                cpa16(S + 0*128*STR_ + row*STR_ + fi*8, Ahp + kt + fi*8);
                cpa16(S + 1*128*STR_ + row*STR_ + fi*8, Alp + kt + fi*8);
                cpa16(S + 2*128*STR_ + row*STR_ + fi*8, Whp + kt + fi*8);
                cpa16(S + 3*128*STR_ + row*STR_ + fi*8, Wlp + kt + fi*8);
            }
            asm volatile("cp.async.commit_group;" ::: "memory");
            asm volatile("cp.async.wait_group 1;" ::: "memory");
        } else {
            asm volatile("cp.async.wait_group 0;" ::: "memory");
        }
        __syncthreads();

        __half* SA_h = smh + (ch & 1) * STAGE_H;
        __half* SA_l = SA_h + 128*STR_;
        __half* SB_h = SA_h + 2*128*STR_;
        __half* SB_l = SA_h + 3*128*STR_;
#pragma unroll
        for (int ks = 0; ks < CHUNK/16; ks++) {
            int kb = ks * 16 + 2 * tg;
            uint32_t ah[4][4], al[4][4];
#pragma unroll
            for (int mi = 0; mi < 4; mi++) {
                int r = (moff + mi*16 + g) * STR_;
                ah[mi][0] = *(const uint32_t*)(SA_h + r + kb);
                ah[mi][1] = *(const uint32_t*)(SA_h + r + 8*STR_ + kb);
                ah[mi][2] = *(const uint32_t*)(SA_h + r + kb + 8);
                ah[mi][3] = *(const uint32_t*)(SA_h + r + 8*STR_ + kb + 8);
                al[mi][0] = *(const uint32_t*)(SA_l + r + kb);
                al[mi][1] = *(const uint32_t*)(SA_l + r + 8*STR_ + kb);
                al[mi][2] = *(const uint32_t*)(SA_l + r + kb + 8);
                al[mi][3] = *(const uint32_t*)(SA_l + r + 8*STR_ + kb + 8);
            }
#pragma unroll
            for (int ni = 0; ni < 4; ni++) {
                int n = (noff + ni*8 + g) * STR_;
                uint32_t bh0 = *(const uint32_t*)(SB_h + n + kb);
                uint32_t bh1 = *(const uint32_t*)(SB_h + n + kb + 8);
                uint32_t bl0 = *(const uint32_t*)(SB_l + n + kb);
                uint32_t bl1 = *(const uint32_t*)(SB_l + n + kb + 8);
#pragma unroll
                for (int mi = 0; mi < 4; mi++) {
                    mma_f16(c_[mi][ni], ah[mi], bh0, bh1);
                    mma_f16(c_[mi][ni], ah[mi], bl0, bl1);
                    mma_f16(c_[mi][ni], al[mi], bh0, bh1);
                }
            }
        }
        __syncthreads();
    }

    // epilogue
#pragma unroll
    for (int ni = 0; ni < 4; ni++) {
        int cc = n0 + noff + ni * 8 + 2 * tg;
        float bx = bias[cc], by = bias[cc + 1];
        if (bias2) { bx += bias2[cc]; by += bias2[cc + 1]; }
#pragma unroll
        for (int mi = 0; mi < 4; mi++) {
            size_t r0 = (size_t)(m0 + moff + mi * 16 + g);
            size_t r1 = r0 + 8;
            float v0 = c_[mi][ni][0] + bx, v1 = c_[mi][ni][1] + by;
            float v2 = c_[mi][ni][2] + bx, v3 = c_[mi][ni][3] + by;
            if (ACT) {
                v0 = fmaxf(v0, 0.f); v1 = fmaxf(v1, 0.f);
                v2 = fmaxf(v2, 0.f); v3 = fmaxf(v3, 0.f);
            }
            if (SPLIT_OUT) {
                *(__half2*)(Ch + r0*N + cc) = sp_hi2(v0, v1);
                *(__half2*)(Cl + r0*N + cc) = sp_lo2(v0, v1);
                *(__half2*)(Ch + r1*N + cc) = sp_hi2(v2, v3);
                *(__half2*)(Cl + r1*N + cc) = sp_lo2(v2, v3);
            } else {
                *(float2*)(C + r0*N + cc) = make_float2(v0, v1);
                *(float2*)(C + r1*N + cc) = make_float2(v2, v3);
            }
        }
    }
}

// ---------------- bin encoder ----------------
__global__ void bin_enc_kernel(const float* __restrict__ bin,
                               const float* __restrict__ W1, const float* __restrict__ b1,
                               const float* __restrict__ W2, const float* __restrict__ b2,
                               float* __restrict__ bb)
{
    __shared__ float h1s[64];
    int b = blockIdx.x, j = threadIdx.x;
    float x0 = bin[b*2], x1 = bin[b*2+1];
    float h = fmaxf(fmaf(x0, W1[j*2], fmaf(x1, W1[j*2+1], b1[j])), 0.f);
    h1s[j] = h;
    __syncthreads();
    float acc = b2[j];
#pragma unroll 8
    for (int k = 0; k < 64; k++) acc = fmaf(h1s[k], W2[j*64 + k], acc);
    bb[b*64 + j] = acc;
}

// ---------------- concat ----------------
__global__ void concat_kernel(const float* __restrict__ p, const float* __restrict__ bb,
                              const float* __restrict__ pos, float* __restrict__ x,
                              __half* __restrict__ xhi, __half* __restrict__ xlo)
{
    int idx = blockIdx.x * 128 + threadIdx.x;
    int r = idx >> 6, c4 = idx & 63;
    int b = r >> 8, s = r & 255;
    float4 v;
    if (c4 < 32)      v = ((const float4*)(p   + (size_t)r*128))[c4];
    else if (c4 < 48) v = ((const float4*)(bb  + (size_t)b*64))[c4-32];
    else              v = ((const float4*)(pos + (size_t)s*64))[c4-48];
    ((float4*)(x + (size_t)r*256))[c4] = v;
    __half2* ph = (__half2*)(xhi + (size_t)r*256);
    __half2* pl = (__half2*)(xlo + (size_t)r*256);
    ph[c4*2]   = sp_hi2(v.x, v.y); pl[c4*2]   = sp_lo2(v.x, v.y);
    ph[c4*2+1] = sp_hi2(v.z, v.w); pl[c4*2+1] = sp_lo2(v.z, v.w);
}

// ---------------- attention: 256 threads, one row/thread ----------------
__global__ __launch_bounds__(256, 2) void attn_kernel(const float* __restrict__ qkv,
                                                      __half* __restrict__ ohi,
                                                      __half* __restrict__ olo)
{
    extern __shared__ float sm[];
    float* Ks = sm;
    float* Vs = sm + 256*32;
    int b = blockIdx.x >> 3, h = blockIdx.x & 7;
    int tid = threadIdx.x;
    const float scale = 0.17677669529663687f;

    {
        const float4* ksrc = (const float4*)(qkv + (size_t)(b*256 + tid)*768 + 256 + h*32);
        const float4* vsrc = (const float4*)(qkv + (size_t)(b*256 + tid)*768 + 512 + h*32);
        float4* kd = (float4*)(Ks + tid*32);
        float4* vd = (float4*)(Vs + tid*32);
#pragma unroll
        for (int i = 0; i < 8; i++) { kd[i] = ksrc[i]; vd[i] = vsrc[i]; }
    }
    float q[32], acc[32];
    {
        const float4* qf = (const float4*)(qkv + (size_t)(b*256 + tid)*768 + h*32);
#pragma unroll
        for (int i = 0; i < 8; i++) {
            float4 t = qf[i];
            q[i*4+0]=t.x; q[i*4+1]=t.y; q[i*4+2]=t.z; q[i*4+3]=t.w;
        }
    }
#pragma unroll
    for (int i = 0; i < 32; i++) acc[i] = 0.f;
    __syncthreads();

    float lsum = 0.f;
    for (int k = 0; k < 256; k++) {
        const float4* kr = (const float4*)(Ks + k*32);
        float s0 = 0.f, s1 = 0.f, s2 = 0.f, s3 = 0.f;
#pragma unroll
        for (int i4 = 0; i4 < 8; i4 += 4) {
            float4 k0 = kr[i4], k1 = kr[i4+1], k2 = kr[i4+2], k3 = kr[i4+3];
            s0 = fmaf(q[i4*4+0],  k0.x, s0); s0 = fmaf(q[i4*4+1],  k0.y, s0);
            s0 = fmaf(q[i4*4+2],  k0.z, s0); s0 = fmaf(q[i4*4+3],  k0.w, s0);
            s1 = fmaf(q[i4*4+4],  k1.x, s1); s1 = fmaf(q[i4*4+5],  k1.y, s1);
            s1 = fmaf(q[i4*4+6],  k1.z, s1); s1 = fmaf(q[i4*4+7],  k1.w, s1);
            s2 = fmaf(q[i4*4+8],  k2.x, s2); s2 = fmaf(q[i4*4+9],  k2.y, s2);
            s2 = fmaf(q[i4*4+10], k2.z, s2); s2 = fmaf(q[i4*4+11], k2.w, s2);
            s3 = fmaf(q[i4*4+12], k3.x, s3); s3 = fmaf(q[i4*4+13], k3.y, s3);
            s3 = fmaf(q[i4*4+14], k3.z, s3); s3 = fmaf(q[i4*4+15], k3.w, s3);
        }
        float p = __expf(((s0 + s1) + (s2 + s3)) * scale);
        lsum += p;
        const float4* vr = (const float4*)(Vs + k*32);
#pragma unroll
        for (int i4 = 0; i4 < 8; i4++) {
            float4 vv = vr[i4];
            acc[i4*4+0] = fmaf(p, vv.x, acc[i4*4+0]);
            acc[i4*4+1] = fmaf(p, vv.y, acc[i4*4+1]);
            acc[i4*4+2] = fmaf(p, vv.z, acc[i4*4+2]);
            acc[i4*4+3] = fmaf(p, vv.w, acc[i4*4+3]);
        }
    }
    float inv = __fdividef(1.f, lsum);
    __half2* oh = (__half2*)(ohi + (size_t)(b*256 + tid)*256 + h*32);
    __half2* ol = (__half2*)(olo + (size_t)(b*256 + tid)*256 + h*32);
#pragma unroll
    for (int i4 = 0; i4 < 8; i4++) {
        float rx = acc[i4*4+0]*inv, ry = acc[i4*4+1]*inv;
        float rz = acc[i4*4+2]*inv, rw = acc[i4*4+3]*inv;
        oh[i4*2]   = sp_hi2(rx, ry); ol[i4*2]   = sp_lo2(rx, ry);
        oh[i4*2+1] = sp_hi2(rz, rw); ol[i4*2+1] = sp_lo2(rz, rw);
    }
}

// ---------------- residual + LayerNorm ----------------
__global__ void add_ln_kernel(const float* __restrict__ x, const float* __restrict__ y,
                              const float* __restrict__ g, const float* __restrict__ be,
                              float* __restrict__ out,
                              __half* __restrict__ ohi, __half* __restrict__ olo)
{
    int warp = threadIdx.x >> 5, lane = threadIdx.x & 31;
    size_t row = (size_t)blockIdx.x * 8 + warp;
    const float4* xr = (const float4*)(x + row*256);
    const float4* yr = (const float4*)(y + row*256);
    float4 a0 = xr[lane*2], a1 = xr[lane*2+1];
    float4 c0 = yr[lane*2], c1 = yr[lane*2+1];
    float v[8];
    v[0]=a0.x+c0.x; v[1]=a0.y+c0.y; v[2]=a0.z+c0.z; v[3]=a0.w+c0.w;
    v[4]=a1.x+c1.x; v[5]=a1.y+c1.y; v[6]=a1.z+c1.z; v[7]=a1.w+c1.w;
    float s = 0.f, s2 = 0.f;
#pragma unroll
    for (int i = 0; i < 8; i++) { s += v[i]; s2 = fmaf(v[i], v[i], s2); }
#pragma unroll
    for (int o = 16; o > 0; o >>= 1) {
        s  += __shfl_xor_sync(0xffffffffu, s,  o);
        s2 += __shfl_xor_sync(0xffffffffu, s2, o);
    }
    float mean = s * (1.f/256.f);
    float var  = s2 * (1.f/256.f) - mean*mean;
    float rstd = rsqrtf(var + 1e-5f);
    const float4* gf = (const float4*)(g + lane*8);
    const float4* bf = (const float4*)(be + lane*8);
    float4 g0 = gf[0], g1 = gf[1], b0 = bf[0], b1 = bf[1];
    float r[8];
    r[0] = (v[0]-mean)*rstd*g0.x + b0.x; r[1] = (v[1]-mean)*rstd*g0.y + b0.y;
    r[2] = (v[2]-mean)*rstd*g0.z + b0.z; r[3] = (v[3]-mean)*rstd*g0.w + b0.w;
    r[4] = (v[4]-mean)*rstd*g1.x + b1.x; r[5] = (v[5]-mean)*rstd*g1.y + b1.y;
    r[6] = (v[6]-mean)*rstd*g1.z + b1.z; r[7] = (v[7]-mean)*rstd*g1.w + b1.w;
    ((float4*)(out + row*256))[lane*2]   = make_float4(r[0], r[1], r[2], r[3]);
    ((float4*)(out + row*256))[lane*2+1] = make_float4(r[4], r[5], r[6], r[7]);
    __half2* ph = (__half2*)(ohi + row*256);
    __half2* pl = (__half2*)(olo + row*256);
#pragma unroll
    for (int i = 0; i < 4; i++) {
        ph[lane*4 + i] = sp_hi2(r[i*2], r[i*2+1]);
        pl[lane*4 + i] = sp_lo2(r[i*2], r[i*2+1]);
    }
}

// ---------------- gather ----------------
__global__ void gather_kernel(const float* __restrict__ enc, const int* __restrict__ target,
                              __half* __restrict__ xhi, __half* __restrict__ xlo)
{
    int idx = blockIdx.x * 256 + threadIdx.x;
    int r = idx >> 6, c4 = idx & 63;
    int t = r >> 5, b = r & 31;
    float4 val = make_float4(0.f, 0.f, 0.f, 0.f);
    if (t > 0) {
        int tgt = target[b*256 + t - 1];
        val = ((const float4*)(enc + (size_t)(b*256 + tgt)*256))[c4];
    }
    __half2* ph = (__half2*)(xhi + (size_t)r*256);
    __half2* pl = (__half2*)(xlo + (size_t)r*256);
    ph[c4*2]   = sp_hi2(val.x, val.y); pl[c4*2]   = sp_lo2(val.x, val.y);
    ph[c4*2+1] = sp_hi2(val.z, val.w); pl[c4*2+1] = sp_lo2(val.z, val.w);
}

// ---------------- lstm init ----------------
__global__ void lstm_init_kernel(int* __restrict__ cnt)
{
    int idx = blockIdx.x * 256 + threadIdx.x;
    if (idx < 32*256) cnt[idx] = 0;
}

// ---------------- LSTM: 256 CTAs, Whh in registers ----------------
__global__ __launch_bounds__(256, 1) void lstm_kernel(
    const float* __restrict__ gin,
    const float* __restrict__ Whh,
    __half* __restrict__ hallhi, __half* __restrict__ halllo,
    float* __restrict__ hbuf,
    int* __restrict__ cnt)
{
    __shared__ float h_s[256];
    __shared__ float g_s[128];
    int b = blockIdx.x >> 3, part = blockIdx.x & 7;
    int tid = threadIdx.x;
    int p = tid >> 1, half = tid & 1;
    int gate = p >> 5, jj = p & 31;
    int col = gate * 256 + part * 32 + jj;

    float w[128];
    {
        const float4* wsrc = (const float4*)(Whh + (size_t)col * 256 + half * 128);
#pragma unroll
        for (int i = 0; i < 32; i++) {
            float4 v = wsrc[i];
            w[i*4+0]=v.x; w[i*4+1]=v.y; w[i*4+2]=v.z; w[i*4+3]=v.w;
        }
    }
    float c = 0.f;
    if (tid < 256) h_s[tid] = 0.f;
    __syncthreads();

    volatile int* vcnt = cnt + b * 256;
    for (int t = 0; t < 256; t++) {
        if (t > 0) {
            if (tid == 0) { while (vcnt[t-1] < LSTM_PARTS) { } }
            __syncthreads();
            const float4* hsrc = (const float4*)(hbuf + ((size_t)((t & 1) * 32 + b)) * 256);
            if (tid < 64) *(float4*)&h_s[tid*4] = __ldcg(hsrc + tid);
            __syncthreads();
        }
        float a0 = 0.f, a1 = 0.f, a2 = 0.f, a3 = 0.f;
        const float4* h4 = (const float4*)&h_s[half * 128];
#pragma unroll
        for (int k4 = 0; k4 < 32; k4 += 4) {
            float4 h0 = h4[k4], h1 = h4[k4+1], h2 = h4[k4+2], h3 = h4[k4+3];
            a0 = fmaf(w[k4*4+0],  h0.x, a0); a0 = fmaf(w[k4*4+1],  h0.y, a0);
            a0 = fmaf(w[k4*4+2],  h0.z, a0); a0 = fmaf(w[k4*4+3],  h0.w, a0);
            a1 = fmaf(w[k4*4+4],  h1.x, a1); a1 = fmaf(w[k4*4+5],  h1.y, a1);
            a1 = fmaf(w[k4*4+6],  h1.z, a1); a1 = fmaf(w[k4*4+7],  h1.w, a1);
            a2 = fmaf(w[k4*4+8],  h2.x, a2); a2 = fmaf(w[k4*4+9],  h2.y, a2);
            a2 = fmaf(w[k4*4+10], h2.z, a2); a2 = fmaf(w[k4*4+11], h2.w, a2);
            a3 = fmaf(w[k4*4+12], h3.x, a3); a3 = fmaf(w[k4*4+13], h3.y, a3);
            a3 = fmaf(w[k4*4+14], h3.z, a3); a3 = fmaf(w[k4*4+15], h3.w, a3);
        }
        float acc = (a0 + a1) + (a2 + a3);
        acc += __shfl_xor_sync(0xffffffffu, acc, 1);
        if (half == 0) {
            float gv = __ldcg(gin + ((size_t)(t*32 + b))*1024 + col);
            g_s[p] = acc + gv;
        }
        __syncthreads();
        if (tid < 32) {
            float gi = g_s[tid], gf = g_s[32+tid], gg = g_s[64+tid], go = g_s[96+tid];
            c = sigf(gf) * c + sigf(gi) * tanh_acc(gg);
            float h = sigf(go) * tanh_acc(c);
            int colh = part*32 + tid;
            hbuf[((size_t)(((t+1) & 1) * 32 + b))*256 + colh] = h;
            __half hh, hl; split2h(h, hh, hl);
            size_t oidx = ((size_t)(t*32 + b))*256 + colh;
            hallhi[oidx] = hh;
            halllo[oidx] = hl;
        }
        __threadfence();
        __syncthreads();
        if (tid == 0) atomicAdd(cnt + b*256 + t, 1);
    }
}

// ---------------- logits: transposed smem, conflict-free reads -------------
#define LP 34
__global__ __launch_bounds__(256, 3) void logits_kernel(
    const float* __restrict__ hp, const float* __restrict__ ep,
    const float* __restrict__ v, float* __restrict__ out)
{
    extern __shared__ float sm[];
    float* hpsT = sm;                 // [256 j][LP] col r = t-row
    float* epsT = sm + 256*LP;        // [256 j][LP] col r = i-row
    float* vs   = sm + 2*256*LP;
    int b = blockIdx.z, tt = blockIdx.y*32, it = blockIdx.x*32;
    int tid = threadIdx.x;
    for (int idx = tid; idx < 32*64; idx += 256) {
        int r = idx >> 6, c4 = idx & 63;
        float4 hv = ((const float4*)(hp + ((size_t)(tt+r)*32 + b)*256))[c4];
        float4 ev = ((const float4*)(ep + ((size_t)b*256 + it + r)*256))[c4];
        int c = c4 * 4;
        hpsT[(c+0)*LP + r] = hv.x; hpsT[(c+1)*LP + r] = hv.y;
        hpsT[(c+2)*LP + r] = hv.z; hpsT[(c+3)*LP + r] = hv.w;
        epsT[(c+0)*LP + r] = ev.x; epsT[(c+1)*LP + r] = ev.y;
        epsT[(c+2)*LP + r] = ev.z; epsT[(c+3)*LP + r] = ev.w;
    }
    if (tid < 64) *(float4*)&vs[tid*4] = ((const float4*)v)[tid];
    __syncthreads();
    int ti = (tid >> 4) * 2, ii = (tid & 15) * 2;
    float s00=0.f, s01=0.f, s10=0.f, s11=0.f;
    for (int j = 0; j < 256; j++) {
        float2 hh = *(const float2*)&hpsT[j*LP + ti];
        float2 ee = *(const float2*)&epsT[j*LP + ii];
        float vj = vs[j];
        s00 = fmaf(vj, tanh_approx(hh.x + ee.x), s00);
        s01 = fmaf(vj, tanh_approx(hh.x + ee.y), s01);
        s10 = fmaf(vj, tanh_approx(hh.y + ee.x), s10);
        s11 = fmaf(vj, tanh_approx(hh.y + ee.y), s11);
    }
    size_t base = ((size_t)b*256 + tt + ti)*256 + it + ii;
    out[base]       = s00; out[base+1]   = s01;
    out[base+256]   = s10; out[base+257] = s11;
}

// ---------------- host ----------------
#define TG_SMEM (2*STAGE_H*2)          // 81920 B
#define LG_SMEM ((2*256*LP + 256)*4)   // 70656 B

extern "C" void kernel_launch(void* const* d_in, const int* in_sizes, int n_in,
                              void* d_out, int out_size)
{
    const float* parts    = (const float*)d_in[0];
    const float* bin_info = (const float*)d_in[1];
    const int*   target   = (const int*)  d_in[2];
    const float* pe_W1 = (const float*)d_in[3];
    const float* pe_b1 = (const float*)d_in[4];
    const float* pe_W2 = (const float*)d_in[5];
    const float* pe_b2 = (const float*)d_in[6];
    const float* be_W1 = (const float*)d_in[7];
    const float* be_b1 = (const float*)d_in[8];
    const float* be_W2 = (const float*)d_in[9];
    const float* be_b2 = (const float*)d_in[10];
    const float* pos_emb = (const float*)d_in[11];
    const float* tr_Wqkv = (const float*)d_in[12];
    const float* tr_bqkv = (const float*)d_in[13];
    const float* tr_Wo   = (const float*)d_in[14];
    const float* tr_bo   = (const float*)d_in[15];
    const float* tr_ln1_g = (const float*)d_in[16];
    const float* tr_ln1_b = (const float*)d_in[17];
    const float* tr_ff_W1 = (const float*)d_in[18];
    const float* tr_ff_b1 = (const float*)d_in[19];
    const float* tr_ff_W2 = (const float*)d_in[20];
    const float* tr_ff_b2 = (const float*)d_in[21];
    const float* tr_ln2_g = (const float*)d_in[22];
    const float* tr_ln2_b = (const float*)d_in[23];
    const float* lstm_Wih = (const float*)d_in[24];
    const float* lstm_Whh = (const float*)d_in[25];
    const float* lstm_bih = (const float*)d_in[26];
    const float* lstm_bhh = (const float*)d_in[27];
    const float* ptr_W = (const float*)d_in[28];
    const float* ptr_b = (const float*)d_in[29];
    const float* ptr_v = (const float*)d_in[30];
    float* out = (float*)d_out;

    float *x_, *qkv_, *tmp_, *bb_, *ep_, *gin_, *hp_, *hbuf_;
    __half *whi_, *wlo_, *phi_, *plo_, *xhi_, *xlo_, *athi_, *atlo_;
    __half *ffhi_, *fflo_, *xihi_, *xilo_, *hahi_, *halo_;
    int* cnt_;
    cudaGetSymbolAddress((void**)&x_,    g_x);
    cudaGetSymbolAddress((void**)&qkv_,  g_qkv);
    cudaGetSymbolAddress((void**)&tmp_,  g_tmp);
    cudaGetSymbolAddress((void**)&bb_,   g_bb);
    cudaGetSymbolAddress((void**)&ep_,   g_eproj);
    cudaGetSymbolAddress((void**)&gin_,  g_gin);
    cudaGetSymbolAddress((void**)&hp_,   g_hp);
    cudaGetSymbolAddress((void**)&hbuf_, g_hbuf);
    cudaGetSymbolAddress((void**)&cnt_,  g_cnt);
    cudaGetSymbolAddress((void**)&whi_,  g_whi);
    cudaGetSymbolAddress((void**)&wlo_,  g_wlo);
    cudaGetSymbolAddress((void**)&phi_,  g_phi);
    cudaGetSymbolAddress((void**)&plo_,  g_plo);
    cudaGetSymbolAddress((void**)&xhi_,  g_xhi);
    cudaGetSymbolAddress((void**)&xlo_,  g_xlo);
    cudaGetSymbolAddress((void**)&athi_, g_athi);
    cudaGetSymbolAddress((void**)&atlo_, g_atlo);
    cudaGetSymbolAddress((void**)&ffhi_, g_ffhi);
    cudaGetSymbolAddress((void**)&fflo_, g_fflo);
    cudaGetSymbolAddress((void**)&xihi_, g_xihi);
    cudaGetSymbolAddress((void**)&xilo_, g_xilo);
    cudaGetSymbolAddress((void**)&hahi_, g_hahi);
    cudaGetSymbolAddress((void**)&halo_, g_halo);

    cudaFuncSetAttribute(attn_kernel,   cudaFuncAttributeMaxDynamicSharedMemorySize, 65536);
    cudaFuncSetAttribute(logits_kernel, cudaFuncAttributeMaxDynamicSharedMemorySize, LG_SMEM);
    cudaFuncSetAttribute(tgemm<1,1,16>, cudaFuncAttributeMaxDynamicSharedMemorySize, TG_SMEM);
    cudaFuncSetAttribute(tgemm<0,0,32>, cudaFuncAttributeMaxDynamicSharedMemorySize, TG_SMEM);
    cudaFuncSetAttribute(tgemm<1,1,32>, cudaFuncAttributeMaxDynamicSharedMemorySize, TG_SMEM);

    // fused weight + input splits (9 segments, one launch)
    SplitSegs ss;
    ss.src[0]=pe_W1;    ss.hi[0]=whi_+OFF_PEW1; ss.lo[0]=wlo_+OFF_PEW1;
    ss.src[1]=pe_W2;    ss.hi[1]=whi_+OFF_PEW2; ss.lo[1]=wlo_+OFF_PEW2;
    ss.src[2]=tr_Wqkv;  ss.hi[2]=whi_+OFF_WQKV; ss.lo[2]=wlo_+OFF_WQKV;
    ss.src[3]=tr_Wo;    ss.hi[3]=whi_+OFF_WO;   ss.lo[3]=wlo_+OFF_WO;
    ss.src[4]=tr_ff_W1; ss.hi[4]=whi_+OFF_FFW1; ss.lo[4]=wlo_+OFF_FFW1;
    ss.src[5]=tr_ff_W2; ss.hi[5]=whi_+OFF_FFW2; ss.lo[5]=wlo_+OFF_FFW2;
    ss.src[6]=lstm_Wih; ss.hi[6]=whi_+OFF_WIH;  ss.lo[6]=wlo_+OFF_WIH;
    ss.src[7]=ptr_W;    ss.hi[7]=whi_+OFF_PTRW; ss.lo[7]=wlo_+OFF_PTRW;
    ss.src[8]=parts;    ss.hi[8]=phi_;          ss.lo[8]=plo_;
    ss.off[0]=0;        ss.off[1]=2048;    ss.off[2]=18432;   ss.off[3]=608256;
    ss.off[4]=804864;   ss.off[5]=1198080; ss.off[6]=1591296; ss.off[7]=1853440;
    ss.off[8]=1918976;  ss.off[9]=2050048;
    split_all_kernel<<<(2050048 + 255)/256, 256>>>(ss);

    // encoders
    bin_enc_kernel<<<32, 64>>>(bin_info, be_W1, be_b1, be_W2, be_b2, bb_);
    tgemm<1,1,16><<<dim3(1,64), 256, TG_SMEM>>>(phi_, plo_, whi_+OFF_PEW1, wlo_+OFF_PEW1,
                                    pe_b1, nullptr, nullptr, athi_, atlo_, ROWS_, 128, 16);
    tgemm<0,0,32><<<dim3(1,64), 256, TG_SMEM>>>(athi_, atlo_, whi_+OFF_PEW2, wlo_+OFF_PEW2,
                                    pe_b2, nullptr, tmp_, nullptr, nullptr, ROWS_, 128, 128);
    concat_kernel<<<4096, 128>>>(tmp_, bb_, pos_emb, x_, xhi_, xlo_);

    // transformer layers
    for (int l = 0; l < 3; l++) {
        tgemm<0,0,32><<<dim3(6,64), 256, TG_SMEM>>>(xhi_, xlo_,
            whi_+OFF_WQKV + (size_t)l*196608, wlo_+OFF_WQKV + (size_t)l*196608,
            tr_bqkv + l*768, nullptr, qkv_, nullptr, nullptr, ROWS_, 768, 256);
        attn_kernel<<<256, 256, 65536>>>(qkv_, athi_, atlo_);
        tgemm<0,0,32><<<dim3(2,64), 256, TG_SMEM>>>(athi_, atlo_,
            whi_+OFF_WO + (size_t)l*65536, wlo_+OFF_WO + (size_t)l*65536,
            tr_bo + l*256, nullptr, tmp_, nullptr, nullptr, ROWS_, 256, 256);
        add_ln_kernel<<<1024, 256>>>(x_, tmp_, tr_ln1_g + l*256, tr_ln1_b + l*256,
                                     x_, xhi_, xlo_);
        tgemm<1,1,32><<<dim3(4,64), 256, TG_SMEM>>>(xhi_, xlo_,
            whi_+OFF_FFW1 + (size_t)l*131072, wlo_+OFF_FFW1 + (size_t)l*131072,
            tr_ff_b1 + l*512, nullptr, nullptr, ffhi_, fflo_, ROWS_, 512, 256);
        tgemm<0,0,32><<<dim3(2,64), 256, TG_SMEM>>>(ffhi_, fflo_,
            whi_+OFF_FFW2 + (size_t)l*131072, wlo_+OFF_FFW2 + (size_t)l*131072,
            tr_ff_b2 + l*256, nullptr, tmp_, nullptr, nullptr, ROWS_, 256, 512);
        add_ln_kernel<<<1024, 256>>>(x_, tmp_, tr_ln2_g + l*256, tr_ln2_b + l*256,
                                     x_, xhi_, xlo_);
    }

    // pointer decode
    tgemm<0,0,32><<<dim3(2,64), 256, TG_SMEM>>>(xhi_, xlo_, whi_+OFF_PTRW, wlo_+OFF_PTRW,
                                    ptr_b, nullptr, ep_, nullptr, nullptr, ROWS_, 256, 256);
    gather_kernel<<<2048, 256>>>(x_, target, xihi_, xilo_);
    tgemm<0,0,32><<<dim3(8,64), 256, TG_SMEM>>>(xihi_, xilo_, whi_+OFF_WIH, wlo_+OFF_WIH,
                                    lstm_bih, lstm_bhh, gin_, nullptr, nullptr, ROWS_, 1024, 256);
    lstm_init_kernel<<<32, 256>>>(cnt_);
    lstm_kernel<<<256, 256>>>(gin_, lstm_Whh, hahi_, halo_, hbuf_, cnt_);
    tgemm<0,0,32><<<dim3(2,64), 256, TG_SMEM>>>(hahi_, halo_, whi_+OFF_PTRW, wlo_+OFF_PTRW,
                                    ptr_b, nullptr, hp_, nullptr, nullptr, ROWS_, 256, 256);
    logits_kernel<<<dim3(8,8,32), 256, LG_SMEM>>>(hp_, ep_, ptr_v, out);
}

// round 15
// speedup vs baseline: 1.0873x; 1.0682x over previous
#include <cuda_runtime.h>
#include <cuda_fp16.h>
#include <cuda_bf16.h>
#include <cstdint>

#define ROWS_ 8192

// weight-split buffer offsets (elements)
#define OFF_PEW1 0
#define OFF_PEW2 2048
#define OFF_WQKV 18432
#define OFF_WO   608256
#define OFF_FFW1 804864
#define OFF_FFW2 1198080
#define OFF_WIH  1591296
#define OFF_PTRW 1853440
#define W_TOTAL  1918976

// ---------------- device scratch ----------------
__device__ float g_x    [ROWS_*256];
__device__ float g_qkv  [ROWS_*768];
__device__ float g_tmp  [ROWS_*256];
__device__ float g_bb   [32*64];
__device__ float g_eproj[ROWS_*256];
__device__ float g_gin  [ROWS_*1024];
__device__ float g_hp   [ROWS_*256];
// fp16 split pairs
__device__ __half g_whi[W_TOTAL], g_wlo[W_TOTAL];
__device__ __half g_phi[ROWS_*16],  g_plo[ROWS_*16];
__device__ __half g_xhi[ROWS_*256], g_xlo[ROWS_*256];
__device__ __half g_athi[ROWS_*256], g_atlo[ROWS_*256];
__device__ __half g_ffhi[ROWS_*512], g_fflo[ROWS_*512];
__device__ __half g_xihi[ROWS_*256], g_xilo[ROWS_*256];
__device__ __half g_hahi[ROWS_*256], g_halo[ROWS_*256];

__device__ __forceinline__ float sigf(float x) {
    return __fdividef(1.f, 1.f + __expf(-x));
}
__device__ __forceinline__ float tanh_acc(float x) {
    float xx = fminf(fmaxf(x, -15.f), 15.f);
    float e  = __expf(2.f * xx);
    return __fdividef(e - 1.f, e + 1.f);
}
__device__ __forceinline__ float tanh_approx(float x) {
    float y;
    asm("tanh.approx.f32 %0, %1;" : "=f"(y) : "f"(x));
    return y;
}
__device__ __forceinline__ void split2h(float x, __half& hi, __half& lo) {
    hi = __float2half_rn(x);
    lo = __float2half_rn(x - __half2float(hi));
}
__device__ __forceinline__ __half2 sp_hi2(float a, float b) {
    return __halves2half2(__float2half_rn(a), __float2half_rn(b));
}
__device__ __forceinline__ __half2 sp_lo2(float a, float b) {
    __half ha = __float2half_rn(a), hb = __float2half_rn(b);
    return __halves2half2(__float2half_rn(a - __half2float(ha)),
                          __float2half_rn(b - __half2float(hb)));
}
__device__ __forceinline__ void cpa16(__half* dst, const __half* src) {
    uint32_t d = (uint32_t)__cvta_generic_to_shared(dst);
    asm volatile("cp.async.cg.shared.global [%0], [%1], 16;" :: "r"(d), "l"(src));
}
__device__ __forceinline__ void st_cluster_f32(uint32_t local_addr, uint32_t rank, float v) {
    uint32_t remote;
    asm volatile("mapa.shared::cluster.u32 %0, %1, %2;"
                 : "=r"(remote) : "r"(local_addr), "r"(rank));
    asm volatile("st.shared::cluster.f32 [%0], %1;" :: "r"(remote), "f"(v) : "memory");
}
#define CLUSTER_SYNC_() do { \
    asm volatile("barrier.cluster.arrive.aligned;" ::: "memory"); \
    asm volatile("barrier.cluster.wait.aligned;" ::: "memory"); } while (0)

// ---------------- fused splitter: 9 segments in one launch ----------------
struct SplitSegs {
    const float* src[9];
    __half* hi[9];
    __half* lo[9];
    int off[10];
};
__global__ void split_all_kernel(SplitSegs s)
{
    int i = blockIdx.x * 256 + threadIdx.x;
    if (i >= s.off[9]) return;
#pragma unroll
    for (int k = 0; k < 9; k++) {
        if (i < s.off[k+1]) {
            int j = i - s.off[k];
            float v = s.src[k][j];
            __half h, l; split2h(v, h, l);
            s.hi[k][j] = h; s.lo[k][j] = l;
            return;
        }
    }
}

// ---------------- fp16 3-term split GEMM, 128x128 tiles, 2-stage cp.async --
__device__ __forceinline__ void mma_f16(float* c, const uint32_t* a,
                                        uint32_t b0, uint32_t b1) {
    asm volatile(
        "mma.sync.aligned.m16n8k16.row.col.f32.f16.f16.f32 "
        "{%0,%1,%2,%3}, {%4,%5,%6,%7}, {%8,%9}, {%0,%1,%2,%3};\n"
        : "+f"(c[0]), "+f"(c[1]), "+f"(c[2]), "+f"(c[3])
        : "r"(a[0]), "r"(a[1]), "r"(a[2]), "r"(a[3]), "r"(b0), "r"(b1));
}

#define STR_ 40             // 80B row stride: word-bank 20g mod 32 all-distinct
#define STAGE_H (4*128*STR_)

template<int ACT, int SPLIT_OUT, int CHUNK>
__global__ __launch_bounds__(256, 2) void tgemm(
    const __half* __restrict__ Ah, const __half* __restrict__ Al,
    const __half* __restrict__ Wh, const __half* __restrict__ Wl,
    const float* __restrict__ bias, const float* __restrict__ bias2,
    float* __restrict__ C, __half* __restrict__ Ch, __half* __restrict__ Cl,
    int M, int N, int K)
{
    extern __shared__ __half smh[];
    int tid = threadIdx.x;
    int m0 = blockIdx.y * 128, n0 = blockIdx.x * 128;
    int warp = tid >> 5, lane = tid & 31;
    int g = lane >> 2, tg = lane & 3;
    int moff = (warp >> 2) * 64, noff = (warp & 3) * 32;

    constexpr int F4 = CHUNK / 16;
    int row = tid >> 1;
    int fbase = (tid & 1) * F4;

    const __half* Ahp = Ah + (size_t)(m0 + row) * K;
    const __half* Alp = Al + (size_t)(m0 + row) * K;
    const __half* Whp = Wh + (size_t)(n0 + row) * K;
    const __half* Wlp = Wl + (size_t)(n0 + row) * K;

    float c_[4][4][4];
#pragma unroll
    for (int i = 0; i < 4; i++)
#pragma unroll
        for (int j = 0; j < 4; j++)
#pragma unroll
            for (int r = 0; r < 4; r++) c_[i][j][r] = 0.f;

    int nch = K / CHUNK;

    {
        __half* S = smh;
#pragma unroll
        for (int j = 0; j < F4; j++) {
            int fi = fbase + j;
            cpa16(S + 0*128*STR_ + row*STR_ + fi*8, Ahp + fi*8);
            cpa16(S + 1*128*STR_ + row*STR_ + fi*8, Alp + fi*8);
            cpa16(S + 2*128*STR_ + row*STR_ + fi*8, Whp + fi*8);
            cpa16(S + 3*128*STR_ + row*STR_ + fi*8, Wlp + fi*8);
        }
        asm volatile("cp.async.commit_group;" ::: "memory");
    }

    for (int ch = 0; ch < nch; ch++) {
        if (ch + 1 < nch) {
            __half* S = smh + ((ch + 1) & 1) * STAGE_H;
            int kt = (ch + 1) * CHUNK;
#pragma unroll
            for (int j = 0; j < F4; j++) {
                int fi = fbase + j;
                cpa16(S + 0*128*STR_ + row*STR_ + fi*8, Ahp + kt + fi*8);
                cpa16(S + 1*128*STR_ + row*STR_ + fi*8, Alp + kt + fi*8);
                cpa16(S + 2*128*STR_ + row*STR_ + fi*8, Whp + kt + fi*8);
                cpa16(S + 3*128*STR_ + row*STR_ + fi*8, Wlp + kt + fi*8);
            }
            asm volatile("cp.async.commit_group;" ::: "memory");
            asm volatile("cp.async.wait_group 1;" ::: "memory");
        } else {
            asm volatile("cp.async.wait_group 0;" ::: "memory");
        }
        __syncthreads();

        __half* SA_h = smh + (ch & 1) * STAGE_H;
        __half* SA_l = SA_h + 128*STR_;
        __half* SB_h = SA_h + 2*128*STR_;
        __half* SB_l = SA_h + 3*128*STR_;
#pragma unroll
        for (int ks = 0; ks < CHUNK/16; ks++) {
            int kb = ks * 16 + 2 * tg;
            uint32_t ah[4][4], al[4][4];
#pragma unroll
            for (int mi = 0; mi < 4; mi++) {
                int r = (moff + mi*16 + g) * STR_;
                ah[mi][0] = *(const uint32_t*)(SA_h + r + kb);
                ah[mi][1] = *(const uint32_t*)(SA_h + r + 8*STR_ + kb);
                ah[mi][2] = *(const uint32_t*)(SA_h + r + kb + 8);
                ah[mi][3] = *(const uint32_t*)(SA_h + r + 8*STR_ + kb + 8);
                al[mi][0] = *(const uint32_t*)(SA_l + r + kb);
                al[mi][1] = *(const uint32_t*)(SA_l + r + 8*STR_ + kb);
                al[mi][2] = *(const uint32_t*)(SA_l + r + kb + 8);
                al[mi][3] = *(const uint32_t*)(SA_l + r + 8*STR_ + kb + 8);
            }
#pragma unroll
            for (int ni = 0; ni < 4; ni++) {
                int n = (noff + ni*8 + g) * STR_;
                uint32_t bh0 = *(const uint32_t*)(SB_h + n + kb);
                uint32_t bh1 = *(const uint32_t*)(SB_h + n + kb + 8);
                uint32_t bl0 = *(const uint32_t*)(SB_l + n + kb);
                uint32_t bl1 = *(const uint32_t*)(SB_l + n + kb + 8);
#pragma unroll
                for (int mi = 0; mi < 4; mi++) {
                    mma_f16(c_[mi][ni], ah[mi], bh0, bh1);
                    mma_f16(c_[mi][ni], ah[mi], bl0, bl1);
                    mma_f16(c_[mi][ni], al[mi], bh0, bh1);
                }
            }
        }
        __syncthreads();
    }

#pragma unroll
    for (int ni = 0; ni < 4; ni++) {
        int cc = n0 + noff + ni * 8 + 2 * tg;
        float bx = bias[cc], by = bias[cc + 1];
        if (bias2) { bx += bias2[cc]; by += bias2[cc + 1]; }
#pragma unroll
        for (int mi = 0; mi < 4; mi++) {
            size_t r0 = (size_t)(m0 + moff + mi * 16 + g);
            size_t r1 = r0 + 8;
            float v0 = c_[mi][ni][0] + bx, v1 = c_[mi][ni][1] + by;
            float v2 = c_[mi][ni][2] + bx, v3 = c_[mi][ni][3] + by;
            if (ACT) {
                v0 = fmaxf(v0, 0.f); v1 = fmaxf(v1, 0.f);
                v2 = fmaxf(v2, 0.f); v3 = fmaxf(v3, 0.f);
            }
            if (SPLIT_OUT) {
                *(__half2*)(Ch + r0*N + cc) = sp_hi2(v0, v1);
                *(__half2*)(Cl + r0*N + cc) = sp_lo2(v0, v1);
                *(__half2*)(Ch + r1*N + cc) = sp_hi2(v2, v3);
                *(__half2*)(Cl + r1*N + cc) = sp_lo2(v2, v3);
            } else {
                *(float2*)(C + r0*N + cc) = make_float2(v0, v1);
                *(float2*)(C + r1*N + cc) = make_float2(v2, v3);
            }
        }
    }
}

// ---------------- bin encoder ----------------
__global__ void bin_enc_kernel(const float* __restrict__ bin,
                               const float* __restrict__ W1, const float* __restrict__ b1,
                               const float* __restrict__ W2, const float* __restrict__ b2,
                               float* __restrict__ bb)
{
    __shared__ float h1s[64];
    int b = blockIdx.x, j = threadIdx.x;
    float x0 = bin[b*2], x1 = bin[b*2+1];
    float h = fmaxf(fmaf(x0, W1[j*2], fmaf(x1, W1[j*2+1], b1[j])), 0.f);
    h1s[j] = h;
    __syncthreads();
    float acc = b2[j];
#pragma unroll 8
    for (int k = 0; k < 64; k++) acc = fmaf(h1s[k], W2[j*64 + k], acc);
    bb[b*64 + j] = acc;
}

// ---------------- concat ----------------
__global__ void concat_kernel(const float* __restrict__ p, const float* __restrict__ bb,
                              const float* __restrict__ pos, float* __restrict__ x,
                              __half* __restrict__ xhi, __half* __restrict__ xlo)
{
    int idx = blockIdx.x * 128 + threadIdx.x;
    int r = idx >> 6, c4 = idx & 63;
    int b = r >> 8, s = r & 255;
    float4 v;
    if (c4 < 32)      v = ((const float4*)(p   + (size_t)r*128))[c4];
    else if (c4 < 48) v = ((const float4*)(bb  + (size_t)b*64))[c4-32];
    else              v = ((const float4*)(pos + (size_t)s*64))[c4-48];
    ((float4*)(x + (size_t)r*256))[c4] = v;
    __half2* ph = (__half2*)(xhi + (size_t)r*256);
    __half2* pl = (__half2*)(xlo + (size_t)r*256);
    ph[c4*2]   = sp_hi2(v.x, v.y); pl[c4*2]   = sp_lo2(v.x, v.y);
    ph[c4*2+1] = sp_hi2(v.z, v.w); pl[c4*2+1] = sp_lo2(v.z, v.w);
}

// ---------------- attention: 256 threads, one row/thread ----------------
__global__ __launch_bounds__(256, 2) void attn_kernel(const float* __restrict__ qkv,
                                                      __half* __restrict__ ohi,
                                                      __half* __restrict__ olo)
{
    extern __shared__ float sm[];
    float* Ks = sm;
    float* Vs = sm + 256*32;
    int b = blockIdx.x >> 3, h = blockIdx.x & 7;
    int tid = threadIdx.x;
    const float scale = 0.17677669529663687f;

    {
        const float4* ksrc = (const float4*)(qkv + (size_t)(b*256 + tid)*768 + 256 + h*32);
        const float4* vsrc = (const float4*)(qkv + (size_t)(b*256 + tid)*768 + 512 + h*32);
        float4* kd = (float4*)(Ks + tid*32);
        float4* vd = (float4*)(Vs + tid*32);
#pragma unroll
        for (int i = 0; i < 8; i++) { kd[i] = ksrc[i]; vd[i] = vsrc[i]; }
    }
    float q[32], acc[32];
    {
        const float4* qf = (const float4*)(qkv + (size_t)(b*256 + tid)*768 + h*32);
#pragma unroll
        for (int i = 0; i < 8; i++) {
            float4 t = qf[i];
            q[i*4+0]=t.x; q[i*4+1]=t.y; q[i*4+2]=t.z; q[i*4+3]=t.w;
        }
    }
#pragma unroll
    for (int i = 0; i < 32; i++) acc[i] = 0.f;
    __syncthreads();

    float lsum = 0.f;
    for (int k = 0; k < 256; k++) {
        const float4* kr = (const float4*)(Ks + k*32);
        float s0 = 0.f, s1 = 0.f, s2 = 0.f, s3 = 0.f;
#pragma unroll
        for (int i4 = 0; i4 < 8; i4 += 4) {
            float4 k0 = kr[i4], k1 = kr[i4+1], k2 = kr[i4+2], k3 = kr[i4+3];
            s0 = fmaf(q[i4*4+0],  k0.x, s0); s0 = fmaf(q[i4*4+1],  k0.y, s0);
            s0 = fmaf(q[i4*4+2],  k0.z, s0); s0 = fmaf(q[i4*4+3],  k0.w, s0);
            s1 = fmaf(q[i4*4+4],  k1.x, s1); s1 = fmaf(q[i4*4+5],  k1.y, s1);
            s1 = fmaf(q[i4*4+6],  k1.z, s1); s1 = fmaf(q[i4*4+7],  k1.w, s1);
            s2 = fmaf(q[i4*4+8],  k2.x, s2); s2 = fmaf(q[i4*4+9],  k2.y, s2);
            s2 = fmaf(q[i4*4+10], k2.z, s2); s2 = fmaf(q[i4*4+11], k2.w, s2);
            s3 = fmaf(q[i4*4+12], k3.x, s3); s3 = fmaf(q[i4*4+13], k3.y, s3);
            s3 = fmaf(q[i4*4+14], k3.z, s3); s3 = fmaf(q[i4*4+15], k3.w, s3);
        }
        float p = __expf(((s0 + s1) + (s2 + s3)) * scale);
        lsum += p;
        const float4* vr = (const float4*)(Vs + k*32);
#pragma unroll
        for (int i4 = 0; i4 < 8; i4++) {
            float4 vv = vr[i4];
            acc[i4*4+0] = fmaf(p, vv.x, acc[i4*4+0]);
            acc[i4*4+1] = fmaf(p, vv.y, acc[i4*4+1]);
            acc[i4*4+2] = fmaf(p, vv.z, acc[i4*4+2]);
            acc[i4*4+3] = fmaf(p, vv.w, acc[i4*4+3]);
        }
    }
    float inv = __fdividef(1.f, lsum);
    __half2* oh = (__half2*)(ohi + (size_t)(b*256 + tid)*256 + h*32);
    __half2* ol = (__half2*)(olo + (size_t)(b*256 + tid)*256 + h*32);
#pragma unroll
    for (int i4 = 0; i4 < 8; i4++) {
        float rx = acc[i4*4+0]*inv, ry = acc[i4*4+1]*inv;
        float rz = acc[i4*4+2]*inv, rw = acc[i4*4+3]*inv;
        oh[i4*2]   = sp_hi2(rx, ry); ol[i4*2]   = sp_lo2(rx, ry);
        oh[i4*2+1] = sp_hi2(rz, rw); ol[i4*2+1] = sp_lo2(rz, rw);
    }
}

// ---------------- residual + LayerNorm ----------------
__global__ void add_ln_kernel(const float* __restrict__ x, const float* __restrict__ y,
                              const float* __restrict__ g, const float* __restrict__ be,
                              float* __restrict__ out,
                              __half* __restrict__ ohi, __half* __restrict__ olo)
{
    int warp = threadIdx.x >> 5, lane = threadIdx.x & 31;
    size_t row = (size_t)blockIdx.x * 8 + warp;
    const float4* xr = (const float4*)(x + row*256);
    const float4* yr = (const float4*)(y + row*256);
    float4 a0 = xr[lane*2], a1 = xr[lane*2+1];
    float4 c0 = yr[lane*2], c1 = yr[lane*2+1];
    float v[8];
    v[0]=a0.x+c0.x; v[1]=a0.y+c0.y; v[2]=a0.z+c0.z; v[3]=a0.w+c0.w;
    v[4]=a1.x+c1.x; v[5]=a1.y+c1.y; v[6]=a1.z+c1.z; v[7]=a1.w+c1.w;
    float s = 0.f, s2 = 0.f;
#pragma unroll
    for (int i = 0; i < 8; i++) { s += v[i]; s2 = fmaf(v[i], v[i], s2); }
#pragma unroll
    for (int o = 16; o > 0; o >>= 1) {
        s  += __shfl_xor_sync(0xffffffffu, s,  o);
        s2 += __shfl_xor_sync(0xffffffffu, s2, o);
    }
    float mean = s * (1.f/256.f);
    float var  = s2 * (1.f/256.f) - mean*mean;
    float rstd = rsqrtf(var + 1e-5f);
    const float4* gf = (const float4*)(g + lane*8);
    const float4* bf = (const float4*)(be + lane*8);
    float4 g0 = gf[0], g1 = gf[1], b0 = bf[0], b1 = bf[1];
    float r[8];
    r[0] = (v[0]-mean)*rstd*g0.x + b0.x; r[1] = (v[1]-mean)*rstd*g0.y + b0.y;
    r[2] = (v[2]-mean)*rstd*g0.z + b0.z; r[3] = (v[3]-mean)*rstd*g0.w + b0.w;
    r[4] = (v[4]-mean)*rstd*g1.x + b1.x; r[5] = (v[5]-mean)*rstd*g1.y + b1.y;
    r[6] = (v[6]-mean)*rstd*g1.z + b1.z; r[7] = (v[7]-mean)*rstd*g1.w + b1.w;
    ((float4*)(out + row*256))[lane*2]   = make_float4(r[0], r[1], r[2], r[3]);
    ((float4*)(out + row*256))[lane*2+1] = make_float4(r[4], r[5], r[6], r[7]);
    __half2* ph = (__half2*)(ohi + row*256);
    __half2* pl = (__half2*)(olo + row*256);
#pragma unroll
    for (int i = 0; i < 4; i++) {
        ph[lane*4 + i] = sp_hi2(r[i*2], r[i*2+1]);
        pl[lane*4 + i] = sp_lo2(r[i*2], r[i*2+1]);
    }
}

// ---------------- gather ----------------
__global__ void gather_kernel(const float* __restrict__ enc, const int* __restrict__ target,
                              __half* __restrict__ xhi, __half* __restrict__ xlo)
{
    int idx = blockIdx.x * 256 + threadIdx.x;
    int r = idx >> 6, c4 = idx & 63;
    int t = r >> 5, b = r & 31;
    float4 val = make_float4(0.f, 0.f, 0.f, 0.f);
    if (t > 0) {
        int tgt = target[b*256 + t - 1];
        val = ((const float4*)(enc + (size_t)(b*256 + tgt)*256))[c4];
    }
    __half2* ph = (__half2*)(xhi + (size_t)r*256);
    __half2* pl = (__half2*)(xlo + (size_t)r*256);
    ph[c4*2]   = sp_hi2(val.x, val.y); pl[c4*2]   = sp_lo2(val.x, val.y);
    ph[c4*2+1] = sp_hi2(val.z, val.w); pl[c4*2+1] = sp_lo2(val.z, val.w);
}

// ---------------- LSTM: 8-CTA clusters, DSMEM h-exchange -------------------
// cluster = one batch (8 parts). Each CTA owns 32 h-cols / 128 gate-cols,
// Whh in registers. Per step: compute -> write h to all 8 peers' h_s[nxt]
// via st.shared::cluster -> barrier.cluster (release/acquire orders stores).
__global__ __launch_bounds__(256, 1) __cluster_dims__(8, 1, 1)
void lstm_kernel(
    const float* __restrict__ gin,   // [256*32][1024] row t*32+b
    const float* __restrict__ Whh,   // [1024][256]
    __half* __restrict__ hallhi, __half* __restrict__ halllo)
{
    __shared__ float h_s[2][256];
    __shared__ float g_s[128];
    int b = blockIdx.x >> 3, part = blockIdx.x & 7;
    int tid = threadIdx.x;
    int p = tid >> 1, half = tid & 1;
    int gate = p >> 5, jj = p & 31;
    int col = gate * 256 + part * 32 + jj;

    float w[128];
    {
        const float4* wsrc = (const float4*)(Whh + (size_t)col * 256 + half * 128);
#pragma unroll
        for (int i = 0; i < 32; i++) {
            float4 v = wsrc[i];
            w[i*4+0]=v.x; w[i*4+1]=v.y; w[i*4+2]=v.z; w[i*4+3]=v.w;
        }
    }
    float c = 0.f;
    if (tid < 256) { h_s[0][tid] = 0.f; }
    __syncthreads();
    CLUSTER_SYNC_();   // all peers' smem initialized before any remote write

    for (int t = 0; t < 256; t++) {
        int cur = t & 1, nxt = cur ^ 1;
        float a0 = 0.f, a1 = 0.f, a2 = 0.f, a3 = 0.f;
        const float4* h4 = (const float4*)&h_s[cur][half * 128];
#pragma unroll
        for (int k4 = 0; k4 < 32; k4 += 4) {
            float4 h0 = h4[k4], h1 = h4[k4+1], h2 = h4[k4+2], h3 = h4[k4+3];
            a0 = fmaf(w[k4*4+0],  h0.x, a0); a0 = fmaf(w[k4*4+1],  h0.y, a0);
            a0 = fmaf(w[k4*4+2],  h0.z, a0); a0 = fmaf(w[k4*4+3],  h0.w, a0);
            a1 = fmaf(w[k4*4+4],  h1.x, a1); a1 = fmaf(w[k4*4+5],  h1.y, a1);
            a1 = fmaf(w[k4*4+6],  h1.z, a1); a1 = fmaf(w[k4*4+7],  h1.w, a1);
            a2 = fmaf(w[k4*4+8],  h2.x, a2); a2 = fmaf(w[k4*4+9],  h2.y, a2);
            a2 = fmaf(w[k4*4+10], h2.z, a2); a2 = fmaf(w[k4*4+11], h2.w, a2);
            a3 = fmaf(w[k4*4+12], h3.x, a3); a3 = fmaf(w[k4*4+13], h3.y, a3);
            a3 = fmaf(w[k4*4+14], h3.z, a3); a3 = fmaf(w[k4*4+15], h3.w, a3);
        }
        float acc = (a0 + a1) + (a2 + a3);
        acc += __shfl_xor_sync(0xffffffffu, acc, 1);
        if (half == 0) {
            float gv = __ldcg(gin + ((size_t)(t*32 + b))*1024 + col);
            g_s[p] = acc + gv;
        }
        __syncthreads();
        if (tid < 32) {
            float gi = g_s[tid], gf = g_s[32+tid], gg = g_s[64+tid], go = g_s[96+tid];
            c = sigf(gf) * c + sigf(gi) * tanh_acc(gg);
            float h = sigf(go) * tanh_acc(c);
            int colh = part*32 + tid;
            // broadcast h to all 8 cluster CTAs' h_s[nxt][colh]
            uint32_t laddr = (uint32_t)__cvta_generic_to_shared(&h_s[nxt][colh]);
#pragma unroll
            for (int r = 0; r < 8; r++) st_cluster_f32(laddr, (uint32_t)r, h);
            __half hh, hl; split2h(h, hh, hl);
            size_t oidx = ((size_t)(t*32 + b))*256 + colh;
            hallhi[oidx] = hh;
            halllo[oidx] = hl;
        }
        CLUSTER_SYNC_();
    }
}

// ---------------- logits: transposed smem, conflict-free reads -------------
#define LP 34
__global__ __launch_bounds__(256, 3) void logits_kernel(
    const float* __restrict__ hp, const float* __restrict__ ep,
    const float* __restrict__ v, float* __restrict__ out)
{
    extern __shared__ float sm[];
    float* hpsT = sm;
    float* epsT = sm + 256*LP;
    float* vs   = sm + 2*256*LP;
    int b = blockIdx.z, tt = blockIdx.y*32, it = blockIdx.x*32;
    int tid = threadIdx.x;
    for (int idx = tid; idx < 32*64; idx += 256) {
        int r = idx >> 6, c4 = idx & 63;
        float4 hv = ((const float4*)(hp + ((size_t)(tt+r)*32 + b)*256))[c4];
        float4 ev = ((const float4*)(ep + ((size_t)b*256 + it + r)*256))[c4];
        int c = c4 * 4;
        hpsT[(c+0)*LP + r] = hv.x; hpsT[(c+1)*LP + r] = hv.y;
        hpsT[(c+2)*LP + r] = hv.z; hpsT[(c+3)*LP + r] = hv.w;
        epsT[(c+0)*LP + r] = ev.x; epsT[(c+1)*LP + r] = ev.y;
        epsT[(c+2)*LP + r] = ev.z; epsT[(c+3)*LP + r] = ev.w;
    }
    if (tid < 64) *(float4*)&vs[tid*4] = ((const float4*)v)[tid];
    __syncthreads();
    int ti = (tid >> 4) * 2, ii = (tid & 15) * 2;
    float s00=0.f, s01=0.f, s10=0.f, s11=0.f;
    for (int j = 0; j < 256; j++) {
        float2 hh = *(const float2*)&hpsT[j*LP + ti];
        float2 ee = *(const float2*)&epsT[j*LP + ii];
        float vj = vs[j];
        s00 = fmaf(vj, tanh_approx(hh.x + ee.x), s00);
        s01 = fmaf(vj, tanh_approx(hh.x + ee.y), s01);
        s10 = fmaf(vj, tanh_approx(hh.y + ee.x), s10);
        s11 = fmaf(vj, tanh_approx(hh.y + ee.y), s11);
    }
    size_t base = ((size_t)b*256 + tt + ti)*256 + it + ii;
    out[base]       = s00; out[base+1]   = s01;
    out[base+256]   = s10; out[base+257] = s11;
}

// ---------------- host ----------------
#define TG_SMEM (2*STAGE_H*2)          // 81920 B
#define LG_SMEM ((2*256*LP + 256)*4)   // 70656 B

extern "C" void kernel_launch(void* const* d_in, const int* in_sizes, int n_in,
                              void* d_out, int out_size)
{
    const float* parts    = (const float*)d_in[0];
    const float* bin_info = (const float*)d_in[1];
    const int*   target   = (const int*)  d_in[2];
    const float* pe_W1 = (const float*)d_in[3];
    const float* pe_b1 = (const float*)d_in[4];
    const float* pe_W2 = (const float*)d_in[5];
    const float* pe_b2 = (const float*)d_in[6];
    const float* be_W1 = (const float*)d_in[7];
    const float* be_b1 = (const float*)d_in[8];
    const float* be_W2 = (const float*)d_in[9];
    const float* be_b2 = (const float*)d_in[10];
    const float* pos_emb = (const float*)d_in[11];
    const float* tr_Wqkv = (const float*)d_in[12];
    const float* tr_bqkv = (const float*)d_in[13];
    const float* tr_Wo   = (const float*)d_in[14];
    const float* tr_bo   = (const float*)d_in[15];
    const float* tr_ln1_g = (const float*)d_in[16];
    const float* tr_ln1_b = (const float*)d_in[17];
    const float* tr_ff_W1 = (const float*)d_in[18];
    const float* tr_ff_b1 = (const float*)d_in[19];
    const float* tr_ff_W2 = (const float*)d_in[20];
    const float* tr_ff_b2 = (const float*)d_in[21];
    const float* tr_ln2_g = (const float*)d_in[22];
    const float* tr_ln2_b = (const float*)d_in[23];
    const float* lstm_Wih = (const float*)d_in[24];
    const float* lstm_Whh = (const float*)d_in[25];
    const float* lstm_bih = (const float*)d_in[26];
    const float* lstm_bhh = (const float*)d_in[27];
    const float* ptr_W = (const float*)d_in[28];
    const float* ptr_b = (const float*)d_in[29];
    const float* ptr_v = (const float*)d_in[30];
    float* out = (float*)d_out;

    float *x_, *qkv_, *tmp_, *bb_, *ep_, *gin_, *hp_;
    __half *whi_, *wlo_, *phi_, *plo_, *xhi_, *xlo_, *athi_, *atlo_;
    __half *ffhi_, *fflo_, *xihi_, *xilo_, *hahi_, *halo_;
    cudaGetSymbolAddress((void**)&x_,    g_x);
    cudaGetSymbolAddress((void**)&qkv_,  g_qkv);
    cudaGetSymbolAddress((void**)&tmp_,  g_tmp);
    cudaGetSymbolAddress((void**)&bb_,   g_bb);
    cudaGetSymbolAddress((void**)&ep_,   g_eproj);
    cudaGetSymbolAddress((void**)&gin_,  g_gin);
    cudaGetSymbolAddress((void**)&hp_,   g_hp);
    cudaGetSymbolAddress((void**)&whi_,  g_whi);
    cudaGetSymbolAddress((void**)&wlo_,  g_wlo);
    cudaGetSymbolAddress((void**)&phi_,  g_phi);
    cudaGetSymbolAddress((void**)&plo_,  g_plo);
    cudaGetSymbolAddress((void**)&xhi_,  g_xhi);
    cudaGetSymbolAddress((void**)&xlo_,  g_xlo);
    cudaGetSymbolAddress((void**)&athi_, g_athi);
    cudaGetSymbolAddress((void**)&atlo_, g_atlo);
    cudaGetSymbolAddress((void**)&ffhi_, g_ffhi);
    cudaGetSymbolAddress((void**)&fflo_, g_fflo);
    cudaGetSymbolAddress((void**)&xihi_, g_xihi);
    cudaGetSymbolAddress((void**)&xilo_, g_xilo);
    cudaGetSymbolAddress((void**)&hahi_, g_hahi);
    cudaGetSymbolAddress((void**)&halo_, g_halo);

    cudaFuncSetAttribute(attn_kernel,   cudaFuncAttributeMaxDynamicSharedMemorySize, 65536);
    cudaFuncSetAttribute(logits_kernel, cudaFuncAttributeMaxDynamicSharedMemorySize, LG_SMEM);
    cudaFuncSetAttribute(tgemm<1,1,16>, cudaFuncAttributeMaxDynamicSharedMemorySize, TG_SMEM);
    cudaFuncSetAttribute(tgemm<0,0,32>, cudaFuncAttributeMaxDynamicSharedMemorySize, TG_SMEM);
    cudaFuncSetAttribute(tgemm<1,1,32>, cudaFuncAttributeMaxDynamicSharedMemorySize, TG_SMEM);

    // fused weight + input splits (9 segments, one launch)
    SplitSegs ss;
    ss.src[0]=pe_W1;    ss.hi[0]=whi_+OFF_PEW1; ss.lo[0]=wlo_+OFF_PEW1;
    ss.src[1]=pe_W2;    ss.hi[1]=whi_+OFF_PEW2; ss.lo[1]=wlo_+OFF_PEW2;
    ss.src[2]=tr_Wqkv;  ss.hi[2]=whi_+OFF_WQKV; ss.lo[2]=wlo_+OFF_WQKV;
    ss.src[3]=tr_Wo;    ss.hi[3]=whi_+OFF_WO;   ss.lo[3]=wlo_+OFF_WO;
    ss.src[4]=tr_ff_W1; ss.hi[4]=whi_+OFF_FFW1; ss.lo[4]=wlo_+OFF_FFW1;
    ss.src[5]=tr_ff_W2; ss.hi[5]=whi_+OFF_FFW2; ss.lo[5]=wlo_+OFF_FFW2;
    ss.src[6]=lstm_Wih; ss.hi[6]=whi_+OFF_WIH;  ss.lo[6]=wlo_+OFF_WIH;
    ss.src[7]=ptr_W;    ss.hi[7]=whi_+OFF_PTRW; ss.lo[7]=wlo_+OFF_PTRW;
    ss.src[8]=parts;    ss.hi[8]=phi_;          ss.lo[8]=plo_;
    ss.off[0]=0;        ss.off[1]=2048;    ss.off[2]=18432;   ss.off[3]=608256;
    ss.off[4]=804864;   ss.off[5]=1198080; ss.off[6]=1591296; ss.off[7]=1853440;
    ss.off[8]=1918976;  ss.off[9]=2050048;
    split_all_kernel<<<(2050048 + 255)/256, 256>>>(ss);

    // encoders
    bin_enc_kernel<<<32, 64>>>(bin_info, be_W1, be_b1, be_W2, be_b2, bb_);
    tgemm<1,1,16><<<dim3(1,64), 256, TG_SMEM>>>(phi_, plo_, whi_+OFF_PEW1, wlo_+OFF_PEW1,
                                    pe_b1, nullptr, nullptr, athi_, atlo_, ROWS_, 128, 16);
    tgemm<0,0,32><<<dim3(1,64), 256, TG_SMEM>>>(athi_, atlo_, whi_+OFF_PEW2, wlo_+OFF_PEW2,
                                    pe_b2, nullptr, tmp_, nullptr, nullptr, ROWS_, 128, 128);
    concat_kernel<<<4096, 128>>>(tmp_, bb_, pos_emb, x_, xhi_, xlo_);

    // transformer layers
    for (int l = 0; l < 3; l++) {
        tgemm<0,0,32><<<dim3(6,64), 256, TG_SMEM>>>(xhi_, xlo_,
            whi_+OFF_WQKV + (size_t)l*196608, wlo_+OFF_WQKV + (size_t)l*196608,
            tr_bqkv + l*768, nullptr, qkv_, nullptr, nullptr, ROWS_, 768, 256);
        attn_kernel<<<256, 256, 65536>>>(qkv_, athi_, atlo_);
        tgemm<0,0,32><<<dim3(2,64), 256, TG_SMEM>>>(athi_, atlo_,
            whi_+OFF_WO + (size_t)l*65536, wlo_+OFF_WO + (size_t)l*65536,
            tr_bo + l*256, nullptr, tmp_, nullptr, nullptr, ROWS_, 256, 256);
        add_ln_kernel<<<1024, 256>>>(x_, tmp_, tr_ln1_g + l*256, tr_ln1_b + l*256,
                                     x_, xhi_, xlo_);
        tgemm<1,1,32><<<dim3(4,64), 256, TG_SMEM>>>(xhi_, xlo_,
            whi_+OFF_FFW1 + (size_t)l*131072, wlo_+OFF_FFW1 + (size_t)l*131072,
            tr_ff_b1 + l*512, nullptr, nullptr, ffhi_, fflo_, ROWS_, 512, 256);
        tgemm<0,0,32><<<dim3(2,64), 256, TG_SMEM>>>(ffhi_, fflo_,
            whi_+OFF_FFW2 + (size_t)l*131072, wlo_+OFF_FFW2 + (size_t)l*131072,
            tr_ff_b2 + l*256, nullptr, tmp_, nullptr, nullptr, ROWS_, 256, 512);
        add_ln_kernel<<<1024, 256>>>(x_, tmp_, tr_ln2_g + l*256, tr_ln2_b + l*256,
                                     x_, xhi_, xlo_);
    }

    // pointer decode
    tgemm<0,0,32><<<dim3(2,64), 256, TG_SMEM>>>(xhi_, xlo_, whi_+OFF_PTRW, wlo_+OFF_PTRW,
                                    ptr_b, nullptr, ep_, nullptr, nullptr, ROWS_, 256, 256);
    gather_kernel<<<2048, 256>>>(x_, target, xihi_, xilo_);
    tgemm<0,0,32><<<dim3(8,64), 256, TG_SMEM>>>(xihi_, xilo_, whi_+OFF_WIH, wlo_+OFF_WIH,
                                    lstm_bih, lstm_bhh, gin_, nullptr, nullptr, ROWS_, 1024, 256);
    lstm_kernel<<<256, 256>>>(gin_, lstm_Whh, hahi_, halo_);
    tgemm<0,0,32><<<dim3(2,64), 256, TG_SMEM>>>(hahi_, halo_, whi_+OFF_PTRW, wlo_+OFF_PTRW,
                                    ptr_b, nullptr, hp_, nullptr, nullptr, ROWS_, 256, 256);
    logits_kernel<<<dim3(8,8,32), 256, LG_SMEM>>>(hp_, ep_, ptr_v, out);
}